// round 13
// baseline (speedup 1.0000x reference)
#include <cuda_runtime.h>
#include <cuda_fp16.h>
#include <math_constants.h>
#include <cstdint>

// ---------------- problem constants ----------------
constexpr int B  = 8;
constexpr int S  = 1024;
constexpr int D  = 1024;
constexpr int H  = 16;
constexpr int DK = 64;
constexpr int F  = 4096;
constexpr int M  = B * S;        // 8192 rows
constexpr int N3 = 3 * D;        // 3072 (Q|K|V concat)

// ---------------- scratch (static device memory; no allocation) ----------------
__device__ __align__(128) float g_bqkv[N3];
__device__ __align__(128) float g_Y   [(size_t)M * D];
__device__ __align__(128) float g_X   [(size_t)M * D];
__device__ __align__(128) float g_Z   [(size_t)M * D];

// weight planes (K-major [N][K]) fp16
__device__ __align__(128) __half g_qkv_w[(size_t)N3 * D];
__device__ __align__(128) __half g_wo_w [(size_t)D * D];
__device__ __align__(128) __half g_w1_w [(size_t)F * D];
__device__ __align__(128) __half g_w2_w [(size_t)D * F];

// activation planes (row-major [M][K]) fp16
__device__ __align__(128) __half g_src_p[(size_t)M * D];
__device__ __align__(128) __half g_q_p  [(size_t)M * N3];   // Q|K|V
__device__ __align__(128) __half g_ctx_p[(size_t)M * D];
__device__ __align__(128) __half g_x_p  [(size_t)M * D];
__device__ __align__(128) __half g_hf_p [(size_t)M * F];

// pre-scaled fp16 mask: clamp(-log2e*1e9*mask, -60000)
__device__ __align__(128) __half g_mask_h[(size_t)S * S];

// ---------------- PTX helpers ----------------
__device__ __forceinline__ uint32_t smem_u32(const void* p) {
    uint32_t a;
    asm("{ .reg .u64 t; cvta.to.shared.u64 t, %1; cvt.u32.u64 %0, t; }" : "=r"(a) : "l"(p));
    return a;
}
#define CP16(dst, src) \
    asm volatile("cp.async.cg.shared.global [%0], [%1], 16;" :: "r"(dst), "l"(src) : "memory")
#define CP_COMMIT() asm volatile("cp.async.commit_group;" ::: "memory")
#define CPWG(n)     asm volatile("cp.async.wait_group " #n ";" ::: "memory")

#define LDSM4(r, addr) \
    asm volatile("ldmatrix.sync.aligned.m8n8.x4.shared.b16 {%0, %1, %2, %3}, [%4];" \
        : "=r"((r)[0]), "=r"((r)[1]), "=r"((r)[2]), "=r"((r)[3]) : "r"(addr))
#define LDSM4T(r, addr) \
    asm volatile("ldmatrix.sync.aligned.m8n8.x4.trans.shared.b16 {%0, %1, %2, %3}, [%4];" \
        : "=r"((r)[0]), "=r"((r)[1]), "=r"((r)[2]), "=r"((r)[3]) : "r"(addr))
#define LDSM2T(r, addr) \
    asm volatile("ldmatrix.sync.aligned.m8n8.x2.trans.shared.b16 {%0, %1}, [%2];" \
        : "=r"((r)[0]), "=r"((r)[1]) : "r"(addr))

#define MMA16816(d, a, b) \
    asm volatile("mma.sync.aligned.m16n8k16.row.col.f32.f16.f16.f32 " \
        "{%0, %1, %2, %3}, {%4, %5, %6, %7}, {%8, %9}, {%0, %1, %2, %3};" \
        : "+f"((d)[0]), "+f"((d)[1]), "+f"((d)[2]), "+f"((d)[3]) \
        : "r"((a)[0]), "r"((a)[1]), "r"((a)[2]), "r"((a)[3]), "r"((b)[0]), "r"((b)[1]))

__device__ __forceinline__ uint32_t pack_h2(float x, float y) {
    __half2 h; h.x = __float2half_rn(x); h.y = __float2half_rn(y);
    return *reinterpret_cast<uint32_t*>(&h);
}
__device__ __forceinline__ uint32_t cvt_ex2(float x, float y) {
    uint32_t p;
    asm("cvt.rn.f16x2.f32 %0, %2, %1;" : "=r"(p) : "f"(x), "f"(y));  // hi=y, lo=x
    asm("ex2.approx.f16x2 %0, %0;" : "+r"(p));
    return p;
}
__device__ __forceinline__ float ex2f(float x) {
    float d; asm("ex2.approx.f32 %0, %1;" : "=f"(d) : "f"(x)); return d;
}

// ---------------- unified prep: all conversions in ONE launch ----------------
__device__ __forceinline__ void convW_body(
    const float* __restrict__ W, __half* __restrict__ oh,
    int Kk, int Nn, int bx, int by, int tid, float (*t)[33])
{
    int n0 = bx * 32, k0 = by * 32;
    int tx = tid & 31, ty = tid >> 5;
    #pragma unroll
    for (int i = 0; i < 4; i++)
        t[ty + i * 8][tx] = W[(size_t)(k0 + ty + i * 8) * Nn + n0 + tx];
    __syncthreads();
    #pragma unroll
    for (int i = 0; i < 4; i++) {
        int n = n0 + ty + i * 8;
        oh[(size_t)n * Kk + k0 + tx] = __float2half_rn(t[tx][ty + i * 8]);
    }
}

// direct Wq/Wk/Wv [H][D][DK] -> g_qkv_w [N3][D] fp16 (one pass)
__device__ __forceinline__ void conv_qkv_body(
    const float* __restrict__ W, int m, int h, int dblk, int kblk,
    int tid, float (*t)[33])
{
    int d0 = dblk * 32, k0 = kblk * 32;
    int tx = tid & 31, ty = tid >> 5;
    #pragma unroll
    for (int i = 0; i < 4; i++)
        t[ty + i * 8][tx] = W[(size_t)h * D * DK + (size_t)(d0 + ty + i * 8) * DK + k0 + tx];
    __syncthreads();
    #pragma unroll
    for (int i = 0; i < 4; i++) {
        int n = m * D + h * DK + k0 + ty + i * 8;
        g_qkv_w[(size_t)n * D + d0 + tx] = __float2half_rn(t[tx][ty + i * 8]);
    }
}

constexpr int PB_QKV  = 3072;
constexpr int PB_WO   = PB_QKV  + 1024;
constexpr int PB_W1   = PB_WO   + 4096;
constexpr int PB_W2   = PB_W1   + 4096;
constexpr int PB_SRC  = PB_W2   + 8192;
constexpr int PB_MASK = PB_SRC  + 1024;
constexpr int PB_BIAS = PB_MASK + 12;

__global__ __launch_bounds__(256) void prep2_k(
    const float* __restrict__ Wq, const float* __restrict__ Wk, const float* __restrict__ Wv,
    const float* __restrict__ bq, const float* __restrict__ bk, const float* __restrict__ bv,
    const float* __restrict__ Wo, const float* __restrict__ W1, const float* __restrict__ W2,
    const float* __restrict__ src, const float* __restrict__ mask)
{
    __shared__ float t[32][33];
    int blk = blockIdx.x, tid = threadIdx.x;
    if (blk < PB_QKV) {
        int m = blk >> 10, r = blk & 1023;
        int h = r >> 6, r2 = r & 63;
        const float* W = (m == 0) ? Wq : (m == 1) ? Wk : Wv;
        conv_qkv_body(W, m, h, r2 >> 1, r2 & 1, tid, t);
    } else if (blk < PB_WO) {
        int r = blk - PB_QKV;
        convW_body(Wo, g_wo_w, D, D, r % 32, r / 32, tid, t);
    } else if (blk < PB_W1) {
        int r = blk - PB_WO;
        convW_body(W1, g_w1_w, D, F, r % 128, r / 128, tid, t);
    } else if (blk < PB_W2) {
        int r = blk - PB_W1;
        convW_body(W2, g_w2_w, F, D, r % 32, r / 32, tid, t);
    } else if (blk < PB_SRC) {
        size_t i = ((size_t)(blk - PB_W2) * 256 + tid) * 4;
        float4 v = *reinterpret_cast<const float4*>(src + i);
        *reinterpret_cast<uint2*>(g_src_p + i) =
            make_uint2(pack_h2(v.x, v.y), pack_h2(v.z, v.w));
    } else if (blk < PB_MASK) {
        size_t i = ((size_t)(blk - PB_SRC) * 256 + tid) * 4;
        float4 v = *reinterpret_cast<const float4*>(mask + i);
        const float kk = -1.4426950408889634e9f;
        float a = fmaxf(-60000.f, kk * v.x), b2 = fmaxf(-60000.f, kk * v.y);
        float c = fmaxf(-60000.f, kk * v.z), d = fmaxf(-60000.f, kk * v.w);
        *reinterpret_cast<uint2*>(g_mask_h + i) = make_uint2(pack_h2(a, b2), pack_h2(c, d));
    } else {
        int idx = (blk - PB_MASK) * 256 + tid;
        int m = idx >> 10, k = idx & 1023;
        const float* bb = (m == 0) ? bq : (m == 1) ? bk : bv;
        g_bqkv[idx] = bb[k];
    }
}

// ---------------- HMMA GEMM, 128x256x64 CTA tile, 64x64 warp tiles ----------------
constexpr int GRH   = 72;
constexpr int GRB   = GRH * 2;            // 144 bytes/row
constexpr int APL   = 128 * GRB;          // 18432
constexpr int BPL   = 256 * GRB;          // 36864
constexpr int GSTG  = APL + BPL;          // 55296
constexpr int GEMM_DSMEM = 3 * GSTG;      // 165888

__global__ __launch_bounds__(256, 1) void gemm_mma(
    const __half* __restrict__ Ap, const __half* __restrict__ Bp,
    float* __restrict__ Cf, __half* __restrict__ Chp,
    const float* __restrict__ bias, const float* __restrict__ resid,
    int Nn, int Kk, int relu)
{
    extern __shared__ char smraw[];
    const uint32_t sbase = smem_u32(smraw);
    const int tid  = threadIdx.x;
    const int lane = tid & 31;
    const int wid  = tid >> 5;
    const int wm   = wid & 1;
    const int wn   = wid >> 1;
    const int m0 = blockIdx.y * 128;
    const int n0 = blockIdx.x * 256;
    const int nk = Kk >> 6;

    float acc[4][8][4];
    #pragma unroll
    for (int i = 0; i < 4; i++)
        #pragma unroll
        for (int j = 0; j < 8; j++)
            #pragma unroll
            for (int q = 0; q < 4; q++) acc[i][j][q] = 0.f;

    auto load = [&](int ci, int stage) {
        const uint32_t sb = sbase + stage * GSTG;
        const int k0 = ci << 6;
        #pragma unroll
        for (int p = 0; p < 4; p++) {
            int c = tid + (p << 8);
            int r = c >> 3, seg = c & 7;
            CP16(sb + (uint32_t)(r * GRB + seg * 16),
                 Ap + (size_t)(m0 + r) * Kk + k0 + seg * 8);
        }
        #pragma unroll
        for (int p = 0; p < 8; p++) {
            int c = tid + (p << 8);
            int r = c >> 3, seg = c & 7;
            CP16(sb + APL + (uint32_t)(r * GRB + seg * 16),
                 Bp + (size_t)(n0 + r) * Kk + k0 + seg * 8);
        }
        CP_COMMIT();
    };

    const int l8 = lane & 7, mt = lane >> 3;

    auto compute = [&](int stage) {
        const uint32_t ab = sbase + stage * GSTG;
        const uint32_t bb = ab + APL;
        #pragma unroll
        for (int h = 0; h < 4; h++) {
            uint32_t Af[4][4];
            #pragma unroll
            for (int i = 0; i < 4; i++) {
                int r = wm * 64 + i * 16 + (lane & 15);
                LDSM4(Af[i], ab + (uint32_t)(r * GRB + h * 32 + (lane >> 4) * 16));
            }
            #pragma unroll
            for (int jt = 0; jt < 4; jt++) {
                int nr = wn * 64 + jt * 16 + (mt >> 1) * 8 + l8;
                uint32_t q[4];
                LDSM4(q, bb + (uint32_t)(nr * GRB + h * 32 + (mt & 1) * 16));
                #pragma unroll
                for (int i = 0; i < 4; i++) {
                    MMA16816(acc[i][jt * 2],     Af[i], q);
                    MMA16816(acc[i][jt * 2 + 1], Af[i], q + 2);
                }
            }
        }
    };

    load(0, 0);
    load(1, 1);

    for (int i = 0; i < nk; i++) {
        if (i + 1 < nk) { CPWG(1); } else { CPWG(0); }
        __syncthreads();
        if (i + 2 < nk) load(i + 2, (i + 2) % 3);
        compute(i % 3);
    }

    #pragma unroll
    for (int i = 0; i < 4; i++) {
        int r = m0 + wm * 64 + i * 16 + (lane >> 2);
        #pragma unroll
        for (int j = 0; j < 8; j++) {
            int c = n0 + wn * 64 + j * 8 + (lane & 3) * 2;
            float2 v0 = { acc[i][j][0], acc[i][j][1] };
            float2 v1 = { acc[i][j][2], acc[i][j][3] };
            float2 bv = *reinterpret_cast<const float2*>(bias + c);
            v0.x += bv.x; v0.y += bv.y;
            v1.x += bv.x; v1.y += bv.y;
            if (resid) {
                float2 r0 = *reinterpret_cast<const float2*>(resid + (size_t)r * Nn + c);
                float2 r1 = *reinterpret_cast<const float2*>(resid + (size_t)(r + 8) * Nn + c);
                v0.x += r0.x; v0.y += r0.y;
                v1.x += r1.x; v1.y += r1.y;
            }
            if (relu) {
                v0.x = fmaxf(v0.x, 0.f); v0.y = fmaxf(v0.y, 0.f);
                v1.x = fmaxf(v1.x, 0.f); v1.y = fmaxf(v1.y, 0.f);
            }
            if (Cf) {
                *reinterpret_cast<float2*>(Cf + (size_t)r * Nn + c) = v0;
                *reinterpret_cast<float2*>(Cf + (size_t)(r + 8) * Nn + c) = v1;
            }
            if (Chp) {
                *reinterpret_cast<uint32_t*>(Chp + (size_t)r * Nn + c) = pack_h2(v0.x, v0.y);
                *reinterpret_cast<uint32_t*>(Chp + (size_t)(r + 8) * Nn + c) = pack_h2(v1.x, v1.y);
            }
        }
    }
}

// ---------------- fused flash attention: 8 warps x 16 q-rows, 64-row K/V tiles, 2 CTAs/SM ----------------
constexpr int FR   = 72;
constexpr int FRB  = FR * 2;          // 144 bytes
constexpr int FQPL = 128 * FRB;       // 18432
constexpr int FKPL = 64 * FRB;        // 9216
constexpr int FA_DSMEM = FQPL + 4 * FKPL;  // 55296

__global__ __launch_bounds__(256, 2) void flash_attn(
    const __half* __restrict__ Qp, const __half* __restrict__ maskh,
    __half* __restrict__ Cp)
{
    extern __shared__ char smraw[];
    const uint32_t sb = smem_u32(smraw);
    const int tid  = threadIdx.x;
    const int lane = tid & 31;
    const int wid  = tid >> 5;          // 0..7, 16 q-rows each
    const int bh = blockIdx.y;
    const int b  = bh >> 4, h = bh & 15;
    const int s0 = blockIdx.x * 128;

    const size_t qoff = (size_t)(b * S + s0) * N3 + h * DK;
    const size_t koff = (size_t)b * S * N3 + D + h * DK;
    const size_t voff = koff + D;

    const uint32_t qb = sb;
    auto kstage = [&](int st) { return sb + FQPL + st * FKPL; };
    auto vstage = [&](int st) { return sb + FQPL + (2 + st) * FKPL; };

    // Q loader: 1024 chunks, 4/thread
    auto cpQ = [&]() {
        #pragma unroll
        for (int p = 0; p < 4; p++) {
            int c = tid + (p << 8);
            int r = c >> 3, seg = c & 7;
            CP16(qb + (uint32_t)(r * FRB + seg * 16), Qp + qoff + (size_t)r * N3 + seg * 8);
        }
    };
    // 64-row tile loader: 512 chunks, 2/thread
    auto cpT1 = [&](size_t base, uint32_t dst) {
        #pragma unroll
        for (int p = 0; p < 2; p++) {
            int c = tid + (p << 8);
            int r = c >> 3, seg = c & 7;
            CP16(dst + (uint32_t)(r * FRB + seg * 16), Qp + base + (size_t)r * N3 + seg * 8);
        }
    };

    // init V pad columns (both stages, 64 rows): col 64 = 1.0h, cols 65..71 = 0
    #pragma unroll
    for (int p = 0; p < 2; p++) {
        int idx = tid + (p << 8);                // 0..511
        int stg = idx >> 8, rem = idx & 255;
        int r = rem >> 2, part = rem & 3;
        *reinterpret_cast<uint32_t*>(smraw + FQPL + (2 + stg) * FKPL + r * FRB + 128 + part * 4) =
            (part == 0) ? 0x00003C00u : 0u;
    }

    cpQ();
    cpT1(koff, kstage(0));
    CP_COMMIT();
    cpT1(voff, vstage(0));
    CP_COMMIT();

    const float k1 = 0.125f * 1.4426950408889634f;

    float mrow0 = -1e30f, mrow1 = -1e30f;
    float O[8][4], Oe[4];
    #pragma unroll
    for (int nj = 0; nj < 8; nj++)
        #pragma unroll
        for (int q = 0; q < 4; q++) O[nj][q] = 0.f;
    #pragma unroll
    for (int q = 0; q < 4; q++) Oe[q] = 0.f;

    const int r0 = wid * 16 + (lane >> 2);
    const int l8 = lane & 7, mt = lane >> 3;

    constexpr int NT = S / 64;                   // 16 tiles
    for (int t = 0; t < NT; t++) {
        const int st = t & 1;
        const uint32_t kst = kstage(st), vst = vstage(st);

        if (t + 1 < NT) {
            cpT1(koff + (size_t)(t + 1) * 64 * N3, kstage(st ^ 1));
            CP_COMMIT();
            CPWG(2);
        } else {
            CPWG(1);
        }
        __syncthreads();

        // ---- S = Q K^T  (16 q-rows x 64 k-rows per warp) ----
        float Sr[8][4];
        #pragma unroll
        for (int j = 0; j < 8; j++)
            #pragma unroll
            for (int q = 0; q < 4; q++) Sr[j][q] = 0.f;

        #pragma unroll
        for (int c = 0; c < 4; c++) {
            uint32_t Af[4];
            LDSM4(Af, qb + (uint32_t)((wid * 16 + (lane & 15)) * FRB + c * 32 + (lane >> 4) * 16));
            #pragma unroll
            for (int jj = 0; jj < 4; jj++) {
                uint32_t bd = kst + (uint32_t)((jj * 16 + (mt >> 1) * 8 + l8) * FRB
                                               + c * 32 + (mt & 1) * 16);
                uint32_t bh4[4];
                LDSM4(bh4, bd);
                MMA16816(Sr[jj * 2],     Af, bh4);
                MMA16816(Sr[jj * 2 + 1], Af, bh4 + 2);
            }
        }

        if (t + 1 < NT) {
            cpT1(voff + (size_t)(t + 1) * 64 * N3, vstage(st ^ 1));
            CP_COMMIT();
        }

        // ---- scale + pre-scaled fp16 mask ----
        {
            const __half* mA = maskh + (size_t)(s0 + r0) * S + t * 64;
            const __half* mB = mA + 8 * S;
            #pragma unroll
            for (int j = 0; j < 8; j++) {
                int tc = j * 8 + (lane & 3) * 2;
                float2 ma = __half22float2(*reinterpret_cast<const __half2*>(mA + tc));
                float2 mb = __half22float2(*reinterpret_cast<const __half2*>(mB + tc));
                Sr[j][0] = Sr[j][0] * k1 + ma.x;
                Sr[j][1] = Sr[j][1] * k1 + ma.y;
                Sr[j][2] = Sr[j][2] * k1 + mb.x;
                Sr[j][3] = Sr[j][3] * k1 + mb.y;
            }
        }

        // ---- online max (log2 domain) ----
        float mt0 = -1e30f, mt1 = -1e30f;
        #pragma unroll
        for (int j = 0; j < 8; j++) {
            mt0 = fmaxf(mt0, fmaxf(Sr[j][0], Sr[j][1]));
            mt1 = fmaxf(mt1, fmaxf(Sr[j][2], Sr[j][3]));
        }
        mt0 = fmaxf(mt0, __shfl_xor_sync(~0u, mt0, 1));
        mt0 = fmaxf(mt0, __shfl_xor_sync(~0u, mt0, 2));
        mt1 = fmaxf(mt1, __shfl_xor_sync(~0u, mt1, 1));
        mt1 = fmaxf(mt1, __shfl_xor_sync(~0u, mt1, 2));
        float mn0 = fmaxf(mrow0, mt0), mn1 = fmaxf(mrow1, mt1);
        float a0 = ex2f(mrow0 - mn0), a1 = ex2f(mrow1 - mn1);
        mrow0 = mn0; mrow1 = mn1;
        #pragma unroll
        for (int nj = 0; nj < 8; nj++) {
            O[nj][0] *= a0; O[nj][1] *= a0;
            O[nj][2] *= a1; O[nj][3] *= a1;
        }
        Oe[0] *= a0; Oe[1] *= a0; Oe[2] *= a1; Oe[3] *= a1;

        if (t + 1 < NT) { CPWG(2); } else { CPWG(0); }
        __syncthreads();

        // ---- O += P V with JIT fp16 P conversion (+ones column row sums) ----
        #pragma unroll
        for (int c = 0; c < 4; c++) {
            uint32_t Ph[4];
            Ph[0] = cvt_ex2(Sr[2 * c][0] - mn0, Sr[2 * c][1] - mn0);
            Ph[1] = cvt_ex2(Sr[2 * c][2] - mn1, Sr[2 * c][3] - mn1);
            Ph[2] = cvt_ex2(Sr[2 * c + 1][0] - mn0, Sr[2 * c + 1][1] - mn0);
            Ph[3] = cvt_ex2(Sr[2 * c + 1][2] - mn1, Sr[2 * c + 1][3] - mn1);
            #pragma unroll
            for (int njp = 0; njp < 4; njp++) {
                uint32_t bd = vst + (uint32_t)((c * 16 + ((lane >> 3) & 1) * 8 + l8) * FRB
                                               + (njp * 16 + (lane >> 4) * 8) * 2);
                uint32_t vh4[4];
                LDSM4T(vh4, bd);
                MMA16816(O[njp * 2],     Ph, vh4);
                MMA16816(O[njp * 2 + 1], Ph, vh4 + 2);
            }
            uint32_t ve[2];
            LDSM2T(ve, vst + (uint32_t)((c * 16 + (lane & 15)) * FRB + 128));
            MMA16816(Oe, Ph, ve);
        }
    }

    // ---- write CTX plane ----
    float l0v = __shfl_sync(~0u, Oe[0], lane & 28);
    float l1v = __shfl_sync(~0u, Oe[2], lane & 28);
    const float il0 = 1.f / l0v, il1 = 1.f / l1v;
    const int sg0 = b * S + s0 + r0;
    #pragma unroll
    for (int nj = 0; nj < 8; nj++) {
        int c = h * DK + nj * 8 + (lane & 3) * 2;
        *reinterpret_cast<uint32_t*>(Cp + (size_t)sg0 * D + c) =
            pack_h2(O[nj][0] * il0, O[nj][1] * il0);
        *reinterpret_cast<uint32_t*>(Cp + (size_t)(sg0 + 8) * D + c) =
            pack_h2(O[nj][2] * il1, O[nj][3] * il1);
    }
}

// ---------------- LayerNorm (optional fp16 plane output) ----------------
__global__ __launch_bounds__(256) void layernorm_k(
    const float* __restrict__ in, const float* __restrict__ w,
    const float* __restrict__ bb, float* __restrict__ out,
    __half* __restrict__ oh)
{
    __shared__ float sh1[8], sh2[8], shb[2];
    size_t row = blockIdx.x;
    const float* x = in + row * D;
    int tid = threadIdx.x, lane = tid & 31, wp = tid >> 5;

    float4 v = *reinterpret_cast<const float4*>(x + tid * 4);
    float s = v.x + v.y + v.z + v.w;
    float q = v.x * v.x + v.y * v.y + v.z * v.z + v.w * v.w;
    #pragma unroll
    for (int o = 16; o; o >>= 1) { s += __shfl_down_sync(~0u, s, o); q += __shfl_down_sync(~0u, q, o); }
    if (!lane) { sh1[wp] = s; sh2[wp] = q; }
    __syncthreads();
    if (tid < 32) {
        s = (tid < 8) ? sh1[tid] : 0.f;
        q = (tid < 8) ? sh2[tid] : 0.f;
        #pragma unroll
        for (int o = 4; o; o >>= 1) { s += __shfl_down_sync(~0u, s, o); q += __shfl_down_sync(~0u, q, o); }
        if (!tid) {
            float mu = s * (1.f / D);
            shb[0] = mu;
            shb[1] = rsqrtf(q * (1.f / D) - mu * mu + 1e-5f);
        }
    }
    __syncthreads();
    float mu = shb[0], rs = shb[1];
    float4 wv = *reinterpret_cast<const float4*>(w  + tid * 4);
    float4 bv = *reinterpret_cast<const float4*>(bb + tid * 4);
    float4 o4;
    o4.x = (v.x - mu) * rs * wv.x + bv.x;
    o4.y = (v.y - mu) * rs * wv.y + bv.y;
    o4.z = (v.z - mu) * rs * wv.z + bv.z;
    o4.w = (v.w - mu) * rs * wv.w + bv.w;
    *reinterpret_cast<float4*>(out + row * D + tid * 4) = o4;
    if (oh) {
        *reinterpret_cast<uint2*>(oh + row * D + tid * 4) =
            make_uint2(pack_h2(o4.x, o4.y), pack_h2(o4.z, o4.w));
    }
}

// ---------------- launch ----------------
extern "C" void kernel_launch(void* const* d_in, const int* in_sizes, int n_in,
                              void* d_out, int out_size)
{
    const float* src  = (const float*)d_in[0];
    const float* mask = (const float*)d_in[1];
    const float* Wq   = (const float*)d_in[2];
    const float* bq   = (const float*)d_in[3];
    const float* Wk   = (const float*)d_in[4];
    const float* bk   = (const float*)d_in[5];
    const float* Wv   = (const float*)d_in[6];
    const float* bv   = (const float*)d_in[7];
    const float* Wo   = (const float*)d_in[8];
    const float* bo   = (const float*)d_in[9];
    const float* ln1w = (const float*)d_in[10];
    const float* ln1b = (const float*)d_in[11];
    const float* W1   = (const float*)d_in[12];
    const float* b1   = (const float*)d_in[13];
    const float* W2   = (const float*)d_in[14];
    const float* b2   = (const float*)d_in[15];
    const float* ln2w = (const float*)d_in[16];
    const float* ln2b = (const float*)d_in[17];
    float* out = (float*)d_out;

    float *pbqkv, *pY, *pX, *pZ;
    __half *pqw, *pow_, *p1w, *p2w;
    __half *psp, *pQp, *pcp, *pxp, *php, *pmh;
    cudaGetSymbolAddress((void**)&pbqkv, g_bqkv);
    cudaGetSymbolAddress((void**)&pY,    g_Y);
    cudaGetSymbolAddress((void**)&pX,    g_X);
    cudaGetSymbolAddress((void**)&pZ,    g_Z);
    cudaGetSymbolAddress((void**)&pqw,   g_qkv_w);
    cudaGetSymbolAddress((void**)&pow_,  g_wo_w);
    cudaGetSymbolAddress((void**)&p1w,   g_w1_w);
    cudaGetSymbolAddress((void**)&p2w,   g_w2_w);
    cudaGetSymbolAddress((void**)&psp,   g_src_p);
    cudaGetSymbolAddress((void**)&pQp,   g_q_p);
    cudaGetSymbolAddress((void**)&pcp,   g_ctx_p);
    cudaGetSymbolAddress((void**)&pxp,   g_x_p);
    cudaGetSymbolAddress((void**)&php,   g_hf_p);
    cudaGetSymbolAddress((void**)&pmh,   g_mask_h);

    cudaFuncSetAttribute(gemm_mma,   cudaFuncAttributeMaxDynamicSharedMemorySize, GEMM_DSMEM);
    cudaFuncSetAttribute(flash_attn, cudaFuncAttributeMaxDynamicSharedMemorySize, FA_DSMEM);

    // 1) unified prep (all conversions, one launch)
    prep2_k<<<PB_BIAS, 256>>>(Wq, Wk, Wv, bq, bk, bv, Wo, W1, W2, src, mask);

    // 2) QKV plane = src @ Wqkv + bqkv
    gemm_mma<<<dim3(N3 / 256, M / 128), 256, GEMM_DSMEM>>>(
        psp, pqw, nullptr, pQp, pbqkv, nullptr, N3, D, 0);

    // 3) fused attention -> CTX plane
    flash_attn<<<dim3(S / 128, B * H), 256, FA_DSMEM>>>(pQp, pmh, pcp);

    // 4) Y = src + CTX @ Wo + bo
    gemm_mma<<<dim3(D / 256, M / 128), 256, GEMM_DSMEM>>>(
        pcp, pow_, pY, nullptr, bo, src, D, D, 0);

    // 5) X = LN1(Y)  (+ fp16 plane)
    layernorm_k<<<M, 256>>>(pY, ln1w, ln1b, pX, pxp);

    // 6) Hf plane = relu(X @ W1 + b1)
    gemm_mma<<<dim3(F / 256, M / 128), 256, GEMM_DSMEM>>>(
        pxp, p1w, nullptr, php, b1, nullptr, F, D, 1);

    // 7) Z = X + Hf @ W2 + b2
    gemm_mma<<<dim3(D / 256, M / 128), 256, GEMM_DSMEM>>>(
        php, p2w, pZ, nullptr, b2, pX, D, F, 0);

    // 8) out = LN2(Z)
    layernorm_k<<<M, 256>>>(pZ, ln2w, ln2b, out, nullptr);
}

// round 14
// speedup vs baseline: 1.0436x; 1.0436x over previous
#include <cuda_runtime.h>
#include <cuda_fp16.h>
#include <math_constants.h>
#include <cstdint>

// ---------------- problem constants ----------------
constexpr int B  = 8;
constexpr int S  = 1024;
constexpr int D  = 1024;
constexpr int H  = 16;
constexpr int DK = 64;
constexpr int F  = 4096;
constexpr int M  = B * S;        // 8192 rows
constexpr int N3 = 3 * D;        // 3072 (Q|K|V concat)

// ---------------- scratch (static device memory; no allocation) ----------------
__device__ __align__(128) float g_Wqkv[(size_t)D * N3];
__device__ __align__(128) float g_bqkv[N3];
__device__ __align__(128) float g_Y   [(size_t)M * D];
__device__ __align__(128) float g_X   [(size_t)M * D];
__device__ __align__(128) float g_Z   [(size_t)M * D];

// weight planes (K-major [N][K]) fp16
__device__ __align__(128) __half g_qkv_w[(size_t)N3 * D];
__device__ __align__(128) __half g_wo_w [(size_t)D * D];
__device__ __align__(128) __half g_w1_w [(size_t)F * D];
__device__ __align__(128) __half g_w2_w [(size_t)D * F];

// activation planes (row-major [M][K]) fp16
__device__ __align__(128) __half g_src_p[(size_t)M * D];
__device__ __align__(128) __half g_q_p  [(size_t)M * N3];   // Q|K|V
__device__ __align__(128) __half g_ctx_p[(size_t)M * D];
__device__ __align__(128) __half g_x_p  [(size_t)M * D];
__device__ __align__(128) __half g_hf_p [(size_t)M * F];

// pre-scaled fp16 mask: clamp(-log2e*1e9*mask, -60000)
__device__ __align__(128) __half g_mask_h[(size_t)S * S];

// ---------------- PTX helpers ----------------
__device__ __forceinline__ uint32_t smem_u32(const void* p) {
    uint32_t a;
    asm("{ .reg .u64 t; cvta.to.shared.u64 t, %1; cvt.u32.u64 %0, t; }" : "=r"(a) : "l"(p));
    return a;
}
#define CP16(dst, src) \
    asm volatile("cp.async.cg.shared.global [%0], [%1], 16;" :: "r"(dst), "l"(src) : "memory")
#define CP_COMMIT() asm volatile("cp.async.commit_group;" ::: "memory")
#define CPWG(n)     asm volatile("cp.async.wait_group " #n ";" ::: "memory")

#define LDSM4(r, addr) \
    asm volatile("ldmatrix.sync.aligned.m8n8.x4.shared.b16 {%0, %1, %2, %3}, [%4];" \
        : "=r"((r)[0]), "=r"((r)[1]), "=r"((r)[2]), "=r"((r)[3]) : "r"(addr))
#define LDSM4T(r, addr) \
    asm volatile("ldmatrix.sync.aligned.m8n8.x4.trans.shared.b16 {%0, %1, %2, %3}, [%4];" \
        : "=r"((r)[0]), "=r"((r)[1]), "=r"((r)[2]), "=r"((r)[3]) : "r"(addr))
#define LDSM2T(r, addr) \
    asm volatile("ldmatrix.sync.aligned.m8n8.x2.trans.shared.b16 {%0, %1}, [%2];" \
        : "=r"((r)[0]), "=r"((r)[1]) : "r"(addr))

#define MMA16816(d, a, b) \
    asm volatile("mma.sync.aligned.m16n8k16.row.col.f32.f16.f16.f32 " \
        "{%0, %1, %2, %3}, {%4, %5, %6, %7}, {%8, %9}, {%0, %1, %2, %3};" \
        : "+f"((d)[0]), "+f"((d)[1]), "+f"((d)[2]), "+f"((d)[3]) \
        : "r"((a)[0]), "r"((a)[1]), "r"((a)[2]), "r"((a)[3]), "r"((b)[0]), "r"((b)[1]))

__device__ __forceinline__ uint32_t pack_h2(float x, float y) {
    __half2 h; h.x = __float2half_rn(x); h.y = __float2half_rn(y);
    return *reinterpret_cast<uint32_t*>(&h);
}
__device__ __forceinline__ uint32_t cvt_ex2(float x, float y) {
    uint32_t p;
    asm("cvt.rn.f16x2.f32 %0, %2, %1;" : "=r"(p) : "f"(x), "f"(y));  // hi=y, lo=x
    asm("ex2.approx.f16x2 %0, %0;" : "+r"(p));
    return p;
}
__device__ __forceinline__ float ex2f(float x) {
    float d; asm("ex2.approx.f32 %0, %1;" : "=f"(d) : "f"(x)); return d;
}

// ---------------- prep stage 1: fp32 QKV weight concat + bias ----------------
__global__ __launch_bounds__(256) void prep_k(
    const float* __restrict__ Wq, const float* __restrict__ Wk, const float* __restrict__ Wv,
    const float* __restrict__ bq, const float* __restrict__ bk, const float* __restrict__ bv)
{
    int idx = blockIdx.x * blockDim.x + threadIdx.x;
    int total = H * D * DK;
    if (idx < total) {
        int h   = idx / (D * DK);
        int rem = idx - h * (D * DK);
        int d   = rem / DK;
        int k   = rem - d * DK;
        size_t dst = (size_t)d * N3 + h * DK + k;
        g_Wqkv[dst        ] = Wq[idx];
        g_Wqkv[dst + D    ] = Wk[idx];
        g_Wqkv[dst + 2 * D] = Wv[idx];
    }
    if (idx < D) {
        g_bqkv[idx        ] = bq[idx];
        g_bqkv[idx + D    ] = bk[idx];
        g_bqkv[idx + 2 * D] = bv[idx];
    }
}

// ---------------- prep stage 2: all conversions in one launch ----------------
__device__ __forceinline__ void convW_body(
    const float* __restrict__ W, __half* __restrict__ oh,
    int Kk, int Nn, int bx, int by, int tid, float (*t)[33])
{
    int n0 = bx * 32, k0 = by * 32;
    int tx = tid & 31, ty = tid >> 5;
    #pragma unroll
    for (int i = 0; i < 4; i++)
        t[ty + i * 8][tx] = W[(size_t)(k0 + ty + i * 8) * Nn + n0 + tx];
    __syncthreads();
    #pragma unroll
    for (int i = 0; i < 4; i++) {
        int n = n0 + ty + i * 8;
        oh[(size_t)n * Kk + k0 + tx] = __float2half_rn(t[tx][ty + i * 8]);
    }
}

constexpr int PB_QKV  = 3072;             // (96 x 32)
constexpr int PB_WO   = PB_QKV  + 1024;
constexpr int PB_W1   = PB_WO   + 4096;
constexpr int PB_W2   = PB_W1   + 4096;
constexpr int PB_SRC  = PB_W2   + 8192;
constexpr int PB_MASK = PB_SRC  + 1024;

__global__ __launch_bounds__(256) void prep2_k(
    const float* __restrict__ Wo, const float* __restrict__ W1, const float* __restrict__ W2,
    const float* __restrict__ src, const float* __restrict__ mask)
{
    __shared__ float t[32][33];
    int blk = blockIdx.x, tid = threadIdx.x;
    if (blk < PB_QKV) {
        convW_body(g_Wqkv, g_qkv_w, D, N3, blk % 96, blk / 96, tid, t);
    } else if (blk < PB_WO) {
        int r = blk - PB_QKV;
        convW_body(Wo, g_wo_w, D, D, r % 32, r / 32, tid, t);
    } else if (blk < PB_W1) {
        int r = blk - PB_WO;
        convW_body(W1, g_w1_w, D, F, r % 128, r / 128, tid, t);
    } else if (blk < PB_W2) {
        int r = blk - PB_W1;
        convW_body(W2, g_w2_w, F, D, r % 32, r / 32, tid, t);
    } else if (blk < PB_SRC) {
        size_t i = ((size_t)(blk - PB_W2) * 256 + tid) * 4;
        float4 v = *reinterpret_cast<const float4*>(src + i);
        *reinterpret_cast<uint2*>(g_src_p + i) =
            make_uint2(pack_h2(v.x, v.y), pack_h2(v.z, v.w));
    } else {
        size_t i = ((size_t)(blk - PB_SRC) * 256 + tid) * 4;
        float4 v = *reinterpret_cast<const float4*>(mask + i);
        const float kk = -1.4426950408889634e9f;
        float a = fmaxf(-60000.f, kk * v.x), b2 = fmaxf(-60000.f, kk * v.y);
        float c = fmaxf(-60000.f, kk * v.z), d = fmaxf(-60000.f, kk * v.w);
        *reinterpret_cast<uint2*>(g_mask_h + i) = make_uint2(pack_h2(a, b2), pack_h2(c, d));
    }
}

// ---------------- HMMA GEMM: 128x256x64 CTA tile, 512 threads, 16 warps x 32x64 ----------------
constexpr int GRH   = 72;
constexpr int GRB   = GRH * 2;            // 144 bytes/row
constexpr int APL   = 128 * GRB;          // 18432
constexpr int BPL   = 256 * GRB;          // 36864
constexpr int GSTG  = APL + BPL;          // 55296
constexpr int GEMM_DSMEM = 3 * GSTG;      // 165888

__global__ __launch_bounds__(512, 1) void gemm_mma(
    const __half* __restrict__ Ap, const __half* __restrict__ Bp,
    float* __restrict__ Cf, __half* __restrict__ Chp,
    const float* __restrict__ bias, const float* __restrict__ resid,
    int Nn, int Kk, int relu)
{
    extern __shared__ char smraw[];
    const uint32_t sbase = smem_u32(smraw);
    const int tid  = threadIdx.x;
    const int lane = tid & 31;
    const int wid  = tid >> 5;            // 0..15
    const int wm   = wid & 3;             // 4 warps in M (32 rows each)
    const int wn   = wid >> 2;            // 4 warps in N (64 cols each)
    const int m0 = blockIdx.y * 128;
    const int n0 = blockIdx.x * 256;
    const int nk = Kk >> 6;

    float acc[2][8][4];
    #pragma unroll
    for (int i = 0; i < 2; i++)
        #pragma unroll
        for (int j = 0; j < 8; j++)
            #pragma unroll
            for (int q = 0; q < 4; q++) acc[i][j][q] = 0.f;

    // stage loader: A 1024 + B 2048 chunks, 6 per thread (512 threads)
    auto load = [&](int ci, int stage) {
        const uint32_t sb = sbase + stage * GSTG;
        const int k0 = ci << 6;
        #pragma unroll
        for (int p = 0; p < 2; p++) {
            int c = tid + (p << 9);              // 0..1023
            int r = c >> 3, seg = c & 7;
            CP16(sb + (uint32_t)(r * GRB + seg * 16),
                 Ap + (size_t)(m0 + r) * Kk + k0 + seg * 8);
        }
        #pragma unroll
        for (int p = 0; p < 4; p++) {
            int c = tid + (p << 9);              // 0..2047
            int r = c >> 3, seg = c & 7;
            CP16(sb + APL + (uint32_t)(r * GRB + seg * 16),
                 Bp + (size_t)(n0 + r) * Kk + k0 + seg * 8);
        }
        CP_COMMIT();
    };

    const int l8 = lane & 7, mt = lane >> 3;

    auto compute = [&](int stage) {
        const uint32_t ab = sbase + stage * GSTG;
        const uint32_t bb = ab + APL;
        #pragma unroll
        for (int h = 0; h < 4; h++) {
            uint32_t Af[2][4];
            #pragma unroll
            for (int i = 0; i < 2; i++) {
                int r = wm * 32 + i * 16 + (lane & 15);
                LDSM4(Af[i], ab + (uint32_t)(r * GRB + h * 32 + (lane >> 4) * 16));
            }
            #pragma unroll
            for (int jt = 0; jt < 4; jt++) {
                int nr = wn * 64 + jt * 16 + (mt >> 1) * 8 + l8;
                uint32_t q[4];
                LDSM4(q, bb + (uint32_t)(nr * GRB + h * 32 + (mt & 1) * 16));
                #pragma unroll
                for (int i = 0; i < 2; i++) {
                    MMA16816(acc[i][jt * 2],     Af[i], q);
                    MMA16816(acc[i][jt * 2 + 1], Af[i], q + 2);
                }
            }
        }
    };

    load(0, 0);
    load(1, 1);

    for (int i = 0; i < nk; i++) {
        if (i + 1 < nk) { CPWG(1); } else { CPWG(0); }
        __syncthreads();
        if (i + 2 < nk) load(i + 2, (i + 2) % 3);
        compute(i % 3);
    }

    // epilogue: per warp 32x64 block
    #pragma unroll
    for (int i = 0; i < 2; i++) {
        int r = m0 + wm * 32 + i * 16 + (lane >> 2);
        #pragma unroll
        for (int j = 0; j < 8; j++) {
            int c = n0 + wn * 64 + j * 8 + (lane & 3) * 2;
            float2 v0 = { acc[i][j][0], acc[i][j][1] };
            float2 v1 = { acc[i][j][2], acc[i][j][3] };
            float2 bv = *reinterpret_cast<const float2*>(bias + c);
            v0.x += bv.x; v0.y += bv.y;
            v1.x += bv.x; v1.y += bv.y;
            if (resid) {
                float2 r0 = *reinterpret_cast<const float2*>(resid + (size_t)r * Nn + c);
                float2 r1 = *reinterpret_cast<const float2*>(resid + (size_t)(r + 8) * Nn + c);
                v0.x += r0.x; v0.y += r0.y;
                v1.x += r1.x; v1.y += r1.y;
            }
            if (relu) {
                v0.x = fmaxf(v0.x, 0.f); v0.y = fmaxf(v0.y, 0.f);
                v1.x = fmaxf(v1.x, 0.f); v1.y = fmaxf(v1.y, 0.f);
            }
            if (Cf) {
                *reinterpret_cast<float2*>(Cf + (size_t)r * Nn + c) = v0;
                *reinterpret_cast<float2*>(Cf + (size_t)(r + 8) * Nn + c) = v1;
            }
            if (Chp) {
                *reinterpret_cast<uint32_t*>(Chp + (size_t)r * Nn + c) = pack_h2(v0.x, v0.y);
                *reinterpret_cast<uint32_t*>(Chp + (size_t)(r + 8) * Nn + c) = pack_h2(v1.x, v1.y);
            }
        }
    }
}

// ---------------- fused flash attention: 4 warps x 32 q-rows, 64-row K/V tiles (R11) ----------------
constexpr int FR   = 72;
constexpr int FRB  = FR * 2;          // 144 bytes
constexpr int FQPL = 128 * FRB;       // 18432
constexpr int FKPL = 64 * FRB;        // 9216
constexpr int FA_DSMEM = FQPL + 4 * FKPL;  // 55296

__global__ __launch_bounds__(128, 2) void flash_attn(
    const __half* __restrict__ Qp, const __half* __restrict__ maskh,
    __half* __restrict__ Cp)
{
    extern __shared__ char smraw[];
    const uint32_t sb = smem_u32(smraw);
    const int tid  = threadIdx.x;
    const int lane = tid & 31;
    const int wid  = tid >> 5;          // 0..3, 32 q-rows each
    const int bh = blockIdx.y;
    const int b  = bh >> 4, h = bh & 15;
    const int s0 = blockIdx.x * 128;

    const size_t qoff = (size_t)(b * S + s0) * N3 + h * DK;
    const size_t koff = (size_t)b * S * N3 + D + h * DK;
    const size_t voff = koff + D;

    const uint32_t qb = sb;
    auto kstage = [&](int st) { return sb + FQPL + st * FKPL; };
    auto vstage = [&](int st) { return sb + FQPL + (2 + st) * FKPL; };

    auto cpQ = [&]() {
        #pragma unroll
        for (int p = 0; p < 8; p++) {
            int c = tid + (p << 7);
            int r = c >> 3, seg = c & 7;
            CP16(qb + (uint32_t)(r * FRB + seg * 16), Qp + qoff + (size_t)r * N3 + seg * 8);
        }
    };
    auto cpT1 = [&](size_t base, uint32_t dst) {
        #pragma unroll
        for (int p = 0; p < 4; p++) {
            int c = tid + (p << 7);
            int r = c >> 3, seg = c & 7;
            CP16(dst + (uint32_t)(r * FRB + seg * 16), Qp + base + (size_t)r * N3 + seg * 8);
        }
    };

    // init V pad columns (both stages, 64 rows): col 64 = 1.0h, cols 65..71 = 0
    #pragma unroll
    for (int p = 0; p < 4; p++) {
        int idx = tid + (p << 7);                // 0..511
        int stg = idx >> 8, rem = idx & 255;
        int r = rem >> 2, part = rem & 3;
        *reinterpret_cast<uint32_t*>(smraw + FQPL + (2 + stg) * FKPL + r * FRB + 128 + part * 4) =
            (part == 0) ? 0x00003C00u : 0u;
    }

    cpQ();
    cpT1(koff, kstage(0));
    CP_COMMIT();
    cpT1(voff, vstage(0));
    CP_COMMIT();

    const float k1 = 0.125f * 1.4426950408889634f;

    float mrow[2][2] = { {-1e30f, -1e30f}, {-1e30f, -1e30f} };
    float O[2][8][4], Oe[2][4];
    #pragma unroll
    for (int i = 0; i < 2; i++) {
        #pragma unroll
        for (int nj = 0; nj < 8; nj++)
            #pragma unroll
            for (int q = 0; q < 4; q++) O[i][nj][q] = 0.f;
        #pragma unroll
        for (int q = 0; q < 4; q++) Oe[i][q] = 0.f;
    }

    const int l8 = lane & 7, mt = lane >> 3;

    constexpr int NT = S / 64;                   // 16 tiles
    for (int t = 0; t < NT; t++) {
        const int st = t & 1;
        const uint32_t kst = kstage(st), vst = vstage(st);

        if (t + 1 < NT) {
            cpT1(koff + (size_t)(t + 1) * 64 * N3, kstage(st ^ 1));
            CP_COMMIT();
            CPWG(2);
        } else {
            CPWG(1);
        }
        __syncthreads();

        // ---- S = Q K^T  (32 q-rows x 64 k-rows per warp) ----
        float Sr[2][8][4];
        #pragma unroll
        for (int i = 0; i < 2; i++)
            #pragma unroll
            for (int j = 0; j < 8; j++)
                #pragma unroll
                for (int q = 0; q < 4; q++) Sr[i][j][q] = 0.f;

        #pragma unroll
        for (int c = 0; c < 4; c++) {
            uint32_t Af[2][4];
            #pragma unroll
            for (int i = 0; i < 2; i++)
                LDSM4(Af[i], qb + (uint32_t)((wid * 32 + i * 16 + (lane & 15)) * FRB
                                             + c * 32 + (lane >> 4) * 16));
            #pragma unroll
            for (int jj = 0; jj < 4; jj++) {
                uint32_t bd = kst + (uint32_t)((jj * 16 + (mt >> 1) * 8 + l8) * FRB
                                               + c * 32 + (mt & 1) * 16);
                uint32_t bh4[4];
                LDSM4(bh4, bd);
                #pragma unroll
                for (int i = 0; i < 2; i++) {
                    MMA16816(Sr[i][jj * 2],     Af[i], bh4);
                    MMA16816(Sr[i][jj * 2 + 1], Af[i], bh4 + 2);
                }
            }
        }

        if (t + 1 < NT) {
            cpT1(voff + (size_t)(t + 1) * 64 * N3, vstage(st ^ 1));
            CP_COMMIT();
        }

        // ---- scale + pre-scaled fp16 mask ----
        #pragma unroll
        for (int i = 0; i < 2; i++) {
            const __half* mA = maskh + (size_t)(s0 + wid * 32 + i * 16 + (lane >> 2)) * S + t * 64;
            const __half* mB = mA + 8 * S;
            #pragma unroll
            for (int j = 0; j < 8; j++) {
                int tc = j * 8 + (lane & 3) * 2;
                float2 ma = __half22float2(*reinterpret_cast<const __half2*>(mA + tc));
                float2 mb = __half22float2(*reinterpret_cast<const __half2*>(mB + tc));
                Sr[i][j][0] = Sr[i][j][0] * k1 + ma.x;
                Sr[i][j][1] = Sr[i][j][1] * k1 + ma.y;
                Sr[i][j][2] = Sr[i][j][2] * k1 + mb.x;
                Sr[i][j][3] = Sr[i][j][3] * k1 + mb.y;
            }
        }

        // ---- online max (log2 domain) ----
        float mn[2][2];
        #pragma unroll
        for (int i = 0; i < 2; i++) {
            float mt0 = -1e30f, mt1 = -1e30f;
            #pragma unroll
            for (int j = 0; j < 8; j++) {
                mt0 = fmaxf(mt0, fmaxf(Sr[i][j][0], Sr[i][j][1]));
                mt1 = fmaxf(mt1, fmaxf(Sr[i][j][2], Sr[i][j][3]));
            }
            mt0 = fmaxf(mt0, __shfl_xor_sync(~0u, mt0, 1));
            mt0 = fmaxf(mt0, __shfl_xor_sync(~0u, mt0, 2));
            mt1 = fmaxf(mt1, __shfl_xor_sync(~0u, mt1, 1));
            mt1 = fmaxf(mt1, __shfl_xor_sync(~0u, mt1, 2));
            mn[i][0] = fmaxf(mrow[i][0], mt0);
            mn[i][1] = fmaxf(mrow[i][1], mt1);
            float a0 = ex2f(mrow[i][0] - mn[i][0]);
            float a1 = ex2f(mrow[i][1] - mn[i][1]);
            mrow[i][0] = mn[i][0]; mrow[i][1] = mn[i][1];
            #pragma unroll
            for (int nj = 0; nj < 8; nj++) {
                O[i][nj][0] *= a0; O[i][nj][1] *= a0;
                O[i][nj][2] *= a1; O[i][nj][3] *= a1;
            }
            Oe[i][0] *= a0; Oe[i][1] *= a0; Oe[i][2] *= a1; Oe[i][3] *= a1;
        }

        if (t + 1 < NT) { CPWG(2); } else { CPWG(0); }
        __syncthreads();

        // ---- O += P V with JIT fp16 P conversion (+ones column row sums) ----
        #pragma unroll
        for (int c = 0; c < 4; c++) {
            uint32_t Ph[2][4];
            #pragma unroll
            for (int i = 0; i < 2; i++) {
                Ph[i][0] = cvt_ex2(Sr[i][2 * c][0] - mn[i][0], Sr[i][2 * c][1] - mn[i][0]);
                Ph[i][1] = cvt_ex2(Sr[i][2 * c][2] - mn[i][1], Sr[i][2 * c][3] - mn[i][1]);
                Ph[i][2] = cvt_ex2(Sr[i][2 * c + 1][0] - mn[i][0], Sr[i][2 * c + 1][1] - mn[i][0]);
                Ph[i][3] = cvt_ex2(Sr[i][2 * c + 1][2] - mn[i][1], Sr[i][2 * c + 1][3] - mn[i][1]);
            }
            #pragma unroll
            for (int njp = 0; njp < 4; njp++) {
                uint32_t bd = vst + (uint32_t)((c * 16 + ((lane >> 3) & 1) * 8 + l8) * FRB
                                               + (njp * 16 + (lane >> 4) * 8) * 2);
                uint32_t vh4[4];
                LDSM4T(vh4, bd);
                #pragma unroll
                for (int i = 0; i < 2; i++) {
                    MMA16816(O[i][njp * 2],     Ph[i], vh4);
                    MMA16816(O[i][njp * 2 + 1], Ph[i], vh4 + 2);
                }
            }
            uint32_t ve[2];
            LDSM2T(ve, vst + (uint32_t)((c * 16 + (lane & 15)) * FRB + 128));
            #pragma unroll
            for (int i = 0; i < 2; i++)
                MMA16816(Oe[i], Ph[i], ve);
        }
    }

    // ---- write CTX plane ----
    #pragma unroll
    for (int i = 0; i < 2; i++) {
        float l0v = __shfl_sync(~0u, Oe[i][0], lane & 28);
        float l1v = __shfl_sync(~0u, Oe[i][2], lane & 28);
        const float il0 = 1.f / l0v, il1 = 1.f / l1v;
        const int sg0 = b * S + s0 + wid * 32 + i * 16 + (lane >> 2);
        #pragma unroll
        for (int nj = 0; nj < 8; nj++) {
            int c = h * DK + nj * 8 + (lane & 3) * 2;
            *reinterpret_cast<uint32_t*>(Cp + (size_t)sg0 * D + c) =
                pack_h2(O[i][nj][0] * il0, O[i][nj][1] * il0);
            *reinterpret_cast<uint32_t*>(Cp + (size_t)(sg0 + 8) * D + c) =
                pack_h2(O[i][nj][2] * il1, O[i][nj][3] * il1);
        }
    }
}

// ---------------- LayerNorm (optional fp16 plane output) ----------------
__global__ __launch_bounds__(256) void layernorm_k(
    const float* __restrict__ in, const float* __restrict__ w,
    const float* __restrict__ bb, float* __restrict__ out,
    __half* __restrict__ oh)
{
    __shared__ float sh1[8], sh2[8], shb[2];
    size_t row = blockIdx.x;
    const float* x = in + row * D;
    int tid = threadIdx.x, lane = tid & 31, wp = tid >> 5;

    float4 v = *reinterpret_cast<const float4*>(x + tid * 4);
    float s = v.x + v.y + v.z + v.w;
    float q = v.x * v.x + v.y * v.y + v.z * v.z + v.w * v.w;
    #pragma unroll
    for (int o = 16; o; o >>= 1) { s += __shfl_down_sync(~0u, s, o); q += __shfl_down_sync(~0u, q, o); }
    if (!lane) { sh1[wp] = s; sh2[wp] = q; }
    __syncthreads();
    if (tid < 32) {
        s = (tid < 8) ? sh1[tid] : 0.f;
        q = (tid < 8) ? sh2[tid] : 0.f;
        #pragma unroll
        for (int o = 4; o; o >>= 1) { s += __shfl_down_sync(~0u, s, o); q += __shfl_down_sync(~0u, q, o); }
        if (!tid) {
            float mu = s * (1.f / D);
            shb[0] = mu;
            shb[1] = rsqrtf(q * (1.f / D) - mu * mu + 1e-5f);
        }
    }
    __syncthreads();
    float mu = shb[0], rs = shb[1];
    float4 wv = *reinterpret_cast<const float4*>(w  + tid * 4);
    float4 bv = *reinterpret_cast<const float4*>(bb + tid * 4);
    float4 o4;
    o4.x = (v.x - mu) * rs * wv.x + bv.x;
    o4.y = (v.y - mu) * rs * wv.y + bv.y;
    o4.z = (v.z - mu) * rs * wv.z + bv.z;
    o4.w = (v.w - mu) * rs * wv.w + bv.w;
    *reinterpret_cast<float4*>(out + row * D + tid * 4) = o4;
    if (oh) {
        *reinterpret_cast<uint2*>(oh + row * D + tid * 4) =
            make_uint2(pack_h2(o4.x, o4.y), pack_h2(o4.z, o4.w));
    }
}

// ---------------- launch ----------------
extern "C" void kernel_launch(void* const* d_in, const int* in_sizes, int n_in,
                              void* d_out, int out_size)
{
    const float* src  = (const float*)d_in[0];
    const float* mask = (const float*)d_in[1];
    const float* Wq   = (const float*)d_in[2];
    const float* bq   = (const float*)d_in[3];
    const float* Wk   = (const float*)d_in[4];
    const float* bk   = (const float*)d_in[5];
    const float* Wv   = (const float*)d_in[6];
    const float* bv   = (const float*)d_in[7];
    const float* Wo   = (const float*)d_in[8];
    const float* bo   = (const float*)d_in[9];
    const float* ln1w = (const float*)d_in[10];
    const float* ln1b = (const float*)d_in[11];
    const float* W1   = (const float*)d_in[12];
    const float* b1   = (const float*)d_in[13];
    const float* W2   = (const float*)d_in[14];
    const float* b2   = (const float*)d_in[15];
    const float* ln2w = (const float*)d_in[16];
    const float* ln2b = (const float*)d_in[17];
    float* out = (float*)d_out;

    float *pbqkv, *pY, *pX, *pZ;
    __half *pqw, *pow_, *p1w, *p2w;
    __half *psp, *pQp, *pcp, *pxp, *php, *pmh;
    cudaGetSymbolAddress((void**)&pbqkv, g_bqkv);
    cudaGetSymbolAddress((void**)&pY,    g_Y);
    cudaGetSymbolAddress((void**)&pX,    g_X);
    cudaGetSymbolAddress((void**)&pZ,    g_Z);
    cudaGetSymbolAddress((void**)&pqw,   g_qkv_w);
    cudaGetSymbolAddress((void**)&pow_,  g_wo_w);
    cudaGetSymbolAddress((void**)&p1w,   g_w1_w);
    cudaGetSymbolAddress((void**)&p2w,   g_w2_w);
    cudaGetSymbolAddress((void**)&psp,   g_src_p);
    cudaGetSymbolAddress((void**)&pQp,   g_q_p);
    cudaGetSymbolAddress((void**)&pcp,   g_ctx_p);
    cudaGetSymbolAddress((void**)&pxp,   g_x_p);
    cudaGetSymbolAddress((void**)&php,   g_hf_p);
    cudaGetSymbolAddress((void**)&pmh,   g_mask_h);

    cudaFuncSetAttribute(gemm_mma,   cudaFuncAttributeMaxDynamicSharedMemorySize, GEMM_DSMEM);
    cudaFuncSetAttribute(flash_attn, cudaFuncAttributeMaxDynamicSharedMemorySize, FA_DSMEM);

    // 1) prep: QKV weight concat, then all conversions
    prep_k<<<(H * D * DK + 255) / 256, 256>>>(Wq, Wk, Wv, bq, bk, bv);
    prep2_k<<<PB_MASK, 256>>>(Wo, W1, W2, src, mask);

    // 2) QKV plane = src @ Wqkv + bqkv
    gemm_mma<<<dim3(N3 / 256, M / 128), 512, GEMM_DSMEM>>>(
        psp, pqw, nullptr, pQp, pbqkv, nullptr, N3, D, 0);

    // 3) fused attention -> CTX plane
    flash_attn<<<dim3(S / 128, B * H), 128, FA_DSMEM>>>(pQp, pmh, pcp);

    // 4) Y = src + CTX @ Wo + bo
    gemm_mma<<<dim3(D / 256, M / 128), 512, GEMM_DSMEM>>>(
        pcp, pow_, pY, nullptr, bo, src, D, D, 0);

    // 5) X = LN1(Y)  (+ fp16 plane)
    layernorm_k<<<M, 256>>>(pY, ln1w, ln1b, pX, pxp);

    // 6) Hf plane = relu(X @ W1 + b1)
    gemm_mma<<<dim3(F / 256, M / 128), 512, GEMM_DSMEM>>>(
        pxp, p1w, nullptr, php, b1, nullptr, F, D, 1);

    // 7) Z = X + Hf @ W2 + b2
    gemm_mma<<<dim3(D / 256, M / 128), 512, GEMM_DSMEM>>>(
        php, p2w, pZ, nullptr, b2, pX, D, F, 0);

    // 8) out = LN2(Z)
    layernorm_k<<<M, 256>>>(pZ, ln2w, ln2b, out, nullptr);
}

// round 15
// speedup vs baseline: 1.0463x; 1.0026x over previous
#include <cuda_runtime.h>
#include <cuda_fp16.h>
#include <math_constants.h>
#include <cstdint>

// ---------------- problem constants ----------------
constexpr int B  = 8;
constexpr int S  = 1024;
constexpr int D  = 1024;
constexpr int H  = 16;
constexpr int DK = 64;
constexpr int F  = 4096;
constexpr int M  = B * S;        // 8192 rows
constexpr int N3 = 3 * D;        // 3072 (Q|K|V concat)

// ---------------- scratch (static device memory; no allocation) ----------------
__device__ __align__(128) float g_bqkv[N3];
__device__ __align__(128) float g_Y   [(size_t)M * D];
__device__ __align__(128) float g_X   [(size_t)M * D];
__device__ __align__(128) float g_Z   [(size_t)M * D];

// weight planes (K-major [N][K]) fp16
__device__ __align__(128) __half g_qkv_w[(size_t)N3 * D];
__device__ __align__(128) __half g_wo_w [(size_t)D * D];
__device__ __align__(128) __half g_w1_w [(size_t)F * D];
__device__ __align__(128) __half g_w2_w [(size_t)D * F];

// activation planes (row-major [M][K]) fp16
__device__ __align__(128) __half g_src_p[(size_t)M * D];
__device__ __align__(128) __half g_q_p  [(size_t)M * N3];   // Q|K|V
__device__ __align__(128) __half g_ctx_p[(size_t)M * D];
__device__ __align__(128) __half g_x_p  [(size_t)M * D];
__device__ __align__(128) __half g_hf_p [(size_t)M * F];

// pre-scaled fp16 mask: clamp(-log2e*1e9*mask, -60000)
__device__ __align__(128) __half g_mask_h[(size_t)S * S];

// ---------------- PTX helpers ----------------
__device__ __forceinline__ uint32_t smem_u32(const void* p) {
    uint32_t a;
    asm("{ .reg .u64 t; cvta.to.shared.u64 t, %1; cvt.u32.u64 %0, t; }" : "=r"(a) : "l"(p));
    return a;
}
#define CP16(dst, src) \
    asm volatile("cp.async.cg.shared.global [%0], [%1], 16;" :: "r"(dst), "l"(src) : "memory")
#define CP_COMMIT() asm volatile("cp.async.commit_group;" ::: "memory")
#define CPWG(n)     asm volatile("cp.async.wait_group " #n ";" ::: "memory")

#define LDSM4(r, addr) \
    asm volatile("ldmatrix.sync.aligned.m8n8.x4.shared.b16 {%0, %1, %2, %3}, [%4];" \
        : "=r"((r)[0]), "=r"((r)[1]), "=r"((r)[2]), "=r"((r)[3]) : "r"(addr))
#define LDSM4T(r, addr) \
    asm volatile("ldmatrix.sync.aligned.m8n8.x4.trans.shared.b16 {%0, %1, %2, %3}, [%4];" \
        : "=r"((r)[0]), "=r"((r)[1]), "=r"((r)[2]), "=r"((r)[3]) : "r"(addr))
#define LDSM2T(r, addr) \
    asm volatile("ldmatrix.sync.aligned.m8n8.x2.trans.shared.b16 {%0, %1}, [%2];" \
        : "=r"((r)[0]), "=r"((r)[1]) : "r"(addr))

#define MMA16816(d, a, b) \
    asm volatile("mma.sync.aligned.m16n8k16.row.col.f32.f16.f16.f32 " \
        "{%0, %1, %2, %3}, {%4, %5, %6, %7}, {%8, %9}, {%0, %1, %2, %3};" \
        : "+f"((d)[0]), "+f"((d)[1]), "+f"((d)[2]), "+f"((d)[3]) \
        : "r"((a)[0]), "r"((a)[1]), "r"((a)[2]), "r"((a)[3]), "r"((b)[0]), "r"((b)[1]))

__device__ __forceinline__ uint32_t pack_h2(float x, float y) {
    __half2 h; h.x = __float2half_rn(x); h.y = __float2half_rn(y);
    return *reinterpret_cast<uint32_t*>(&h);
}
__device__ __forceinline__ uint32_t cvt_ex2(float x, float y) {
    uint32_t p;
    asm("cvt.rn.f16x2.f32 %0, %2, %1;" : "=r"(p) : "f"(x), "f"(y));  // hi=y, lo=x
    asm("ex2.approx.f16x2 %0, %0;" : "+r"(p));
    return p;
}
__device__ __forceinline__ float ex2f(float x) {
    float d; asm("ex2.approx.f32 %0, %1;" : "=f"(d) : "f"(x)); return d;
}

// ---------------- unified prep: all conversions in ONE launch ----------------
__device__ __forceinline__ void convW_body(
    const float* __restrict__ W, __half* __restrict__ oh,
    int Kk, int Nn, int bx, int by, int tid, float (*t)[33])
{
    int n0 = bx * 32, k0 = by * 32;
    int tx = tid & 31, ty = tid >> 5;
    #pragma unroll
    for (int i = 0; i < 4; i++)
        t[ty + i * 8][tx] = W[(size_t)(k0 + ty + i * 8) * Nn + n0 + tx];
    __syncthreads();
    #pragma unroll
    for (int i = 0; i < 4; i++) {
        int n = n0 + ty + i * 8;
        oh[(size_t)n * Kk + k0 + tx] = __float2half_rn(t[tx][ty + i * 8]);
    }
}

// direct Wq/Wk/Wv [H][D][DK] -> g_qkv_w [N3][D] fp16 (one pass)
__device__ __forceinline__ void conv_qkv_body(
    const float* __restrict__ W, int m, int h, int dblk, int kblk,
    int tid, float (*t)[33])
{
    int d0 = dblk * 32, k0 = kblk * 32;
    int tx = tid & 31, ty = tid >> 5;
    #pragma unroll
    for (int i = 0; i < 4; i++)
        t[ty + i * 8][tx] = W[(size_t)h * D * DK + (size_t)(d0 + ty + i * 8) * DK + k0 + tx];
    __syncthreads();
    #pragma unroll
    for (int i = 0; i < 4; i++) {
        int n = m * D + h * DK + k0 + ty + i * 8;
        g_qkv_w[(size_t)n * D + d0 + tx] = __float2half_rn(t[tx][ty + i * 8]);
    }
}

constexpr int PB_QKV  = 3072;             // 3 mats x (16h x 32d x 2k)
constexpr int PB_WO   = PB_QKV  + 1024;
constexpr int PB_W1   = PB_WO   + 4096;
constexpr int PB_W2   = PB_W1   + 4096;
constexpr int PB_SRC  = PB_W2   + 8192;
constexpr int PB_MASK = PB_SRC  + 1024;
constexpr int PB_BIAS = PB_MASK + 12;

__global__ __launch_bounds__(256) void prep2_k(
    const float* __restrict__ Wq, const float* __restrict__ Wk, const float* __restrict__ Wv,
    const float* __restrict__ bq, const float* __restrict__ bk, const float* __restrict__ bv,
    const float* __restrict__ Wo, const float* __restrict__ W1, const float* __restrict__ W2,
    const float* __restrict__ src, const float* __restrict__ mask)
{
    __shared__ float t[32][33];
    int blk = blockIdx.x, tid = threadIdx.x;
    if (blk < PB_QKV) {
        int m = blk >> 10, r = blk & 1023;
        int h = r >> 6, r2 = r & 63;
        const float* W = (m == 0) ? Wq : (m == 1) ? Wk : Wv;
        conv_qkv_body(W, m, h, r2 >> 1, r2 & 1, tid, t);
    } else if (blk < PB_WO) {
        int r = blk - PB_QKV;
        convW_body(Wo, g_wo_w, D, D, r % 32, r / 32, tid, t);
    } else if (blk < PB_W1) {
        int r = blk - PB_WO;
        convW_body(W1, g_w1_w, D, F, r % 128, r / 128, tid, t);
    } else if (blk < PB_W2) {
        int r = blk - PB_W1;
        convW_body(W2, g_w2_w, F, D, r % 32, r / 32, tid, t);
    } else if (blk < PB_SRC) {
        size_t i = ((size_t)(blk - PB_W2) * 256 + tid) * 4;
        float4 v = *reinterpret_cast<const float4*>(src + i);
        *reinterpret_cast<uint2*>(g_src_p + i) =
            make_uint2(pack_h2(v.x, v.y), pack_h2(v.z, v.w));
    } else if (blk < PB_MASK) {
        size_t i = ((size_t)(blk - PB_SRC) * 256 + tid) * 4;
        float4 v = *reinterpret_cast<const float4*>(mask + i);
        const float kk = -1.4426950408889634e9f;
        float a = fmaxf(-60000.f, kk * v.x), b2 = fmaxf(-60000.f, kk * v.y);
        float c = fmaxf(-60000.f, kk * v.z), d = fmaxf(-60000.f, kk * v.w);
        *reinterpret_cast<uint2*>(g_mask_h + i) = make_uint2(pack_h2(a, b2), pack_h2(c, d));
    } else {
        int idx = (blk - PB_MASK) * 256 + tid;
        int m = idx >> 10, k = idx & 1023;
        const float* bb = (m == 0) ? bq : (m == 1) ? bk : bv;
        g_bqkv[idx] = bb[k];
    }
}

// ---------------- HMMA GEMM: 128x256x64 CTA tile, 512 threads, 16 warps x 32x64 ----------------
constexpr int GRH   = 72;
constexpr int GRB   = GRH * 2;            // 144 bytes/row
constexpr int APL   = 128 * GRB;          // 18432
constexpr int BPL   = 256 * GRB;          // 36864
constexpr int GSTG  = APL + BPL;          // 55296
constexpr int GEMM_DSMEM = 3 * GSTG;      // 165888

__global__ __launch_bounds__(512, 1) void gemm_mma(
    const __half* __restrict__ Ap, const __half* __restrict__ Bp,
    float* __restrict__ Cf, __half* __restrict__ Chp,
    const float* __restrict__ bias, const float* __restrict__ resid,
    int Nn, int Kk, int relu)
{
    extern __shared__ char smraw[];
    const uint32_t sbase = smem_u32(smraw);
    const int tid  = threadIdx.x;
    const int lane = tid & 31;
    const int wid  = tid >> 5;            // 0..15
    const int wm   = wid & 3;             // 4 warps in M (32 rows each)
    const int wn   = wid >> 2;            // 4 warps in N (64 cols each)
    const int m0 = blockIdx.y * 128;
    const int n0 = blockIdx.x * 256;
    const int nk = Kk >> 6;

    float acc[2][8][4];
    #pragma unroll
    for (int i = 0; i < 2; i++)
        #pragma unroll
        for (int j = 0; j < 8; j++)
            #pragma unroll
            for (int q = 0; q < 4; q++) acc[i][j][q] = 0.f;

    auto load = [&](int ci, int stage) {
        const uint32_t sb = sbase + stage * GSTG;
        const int k0 = ci << 6;
        #pragma unroll
        for (int p = 0; p < 2; p++) {
            int c = tid + (p << 9);
            int r = c >> 3, seg = c & 7;
            CP16(sb + (uint32_t)(r * GRB + seg * 16),
                 Ap + (size_t)(m0 + r) * Kk + k0 + seg * 8);
        }
        #pragma unroll
        for (int p = 0; p < 4; p++) {
            int c = tid + (p << 9);
            int r = c >> 3, seg = c & 7;
            CP16(sb + APL + (uint32_t)(r * GRB + seg * 16),
                 Bp + (size_t)(n0 + r) * Kk + k0 + seg * 8);
        }
        CP_COMMIT();
    };

    const int l8 = lane & 7, mt = lane >> 3;

    auto compute = [&](int stage) {
        const uint32_t ab = sbase + stage * GSTG;
        const uint32_t bb = ab + APL;
        #pragma unroll
        for (int h = 0; h < 4; h++) {
            uint32_t Af[2][4];
            #pragma unroll
            for (int i = 0; i < 2; i++) {
                int r = wm * 32 + i * 16 + (lane & 15);
                LDSM4(Af[i], ab + (uint32_t)(r * GRB + h * 32 + (lane >> 4) * 16));
            }
            #pragma unroll
            for (int jt = 0; jt < 4; jt++) {
                int nr = wn * 64 + jt * 16 + (mt >> 1) * 8 + l8;
                uint32_t q[4];
                LDSM4(q, bb + (uint32_t)(nr * GRB + h * 32 + (mt & 1) * 16));
                #pragma unroll
                for (int i = 0; i < 2; i++) {
                    MMA16816(acc[i][jt * 2],     Af[i], q);
                    MMA16816(acc[i][jt * 2 + 1], Af[i], q + 2);
                }
            }
        }
    };

    load(0, 0);
    load(1, 1);

    for (int i = 0; i < nk; i++) {
        if (i + 1 < nk) { CPWG(1); } else { CPWG(0); }
        __syncthreads();
        if (i + 2 < nk) load(i + 2, (i + 2) % 3);
        compute(i % 3);
    }

    #pragma unroll
    for (int i = 0; i < 2; i++) {
        int r = m0 + wm * 32 + i * 16 + (lane >> 2);
        #pragma unroll
        for (int j = 0; j < 8; j++) {
            int c = n0 + wn * 64 + j * 8 + (lane & 3) * 2;
            float2 v0 = { acc[i][j][0], acc[i][j][1] };
            float2 v1 = { acc[i][j][2], acc[i][j][3] };
            float2 bv = *reinterpret_cast<const float2*>(bias + c);
            v0.x += bv.x; v0.y += bv.y;
            v1.x += bv.x; v1.y += bv.y;
            if (resid) {
                float2 r0 = *reinterpret_cast<const float2*>(resid + (size_t)r * Nn + c);
                float2 r1 = *reinterpret_cast<const float2*>(resid + (size_t)(r + 8) * Nn + c);
                v0.x += r0.x; v0.y += r0.y;
                v1.x += r1.x; v1.y += r1.y;
            }
            if (relu) {
                v0.x = fmaxf(v0.x, 0.f); v0.y = fmaxf(v0.y, 0.f);
                v1.x = fmaxf(v1.x, 0.f); v1.y = fmaxf(v1.y, 0.f);
            }
            if (Cf) {
                *reinterpret_cast<float2*>(Cf + (size_t)r * Nn + c) = v0;
                *reinterpret_cast<float2*>(Cf + (size_t)(r + 8) * Nn + c) = v1;
            }
            if (Chp) {
                *reinterpret_cast<uint32_t*>(Chp + (size_t)r * Nn + c) = pack_h2(v0.x, v0.y);
                *reinterpret_cast<uint32_t*>(Chp + (size_t)(r + 8) * Nn + c) = pack_h2(v1.x, v1.y);
            }
        }
    }
}

// ---------------- fused flash attention: 4 warps x 32 q-rows, 64-row K/V tiles ----------------
// Q fragments hoisted into registers (reused across all 16 K-tiles).
constexpr int FR   = 72;
constexpr int FRB  = FR * 2;          // 144 bytes
constexpr int FQPL = 128 * FRB;       // 18432
constexpr int FKPL = 64 * FRB;        // 9216
constexpr int FA_DSMEM = FQPL + 4 * FKPL;  // 55296

__global__ __launch_bounds__(128, 2) void flash_attn(
    const __half* __restrict__ Qp, const __half* __restrict__ maskh,
    __half* __restrict__ Cp)
{
    extern __shared__ char smraw[];
    const uint32_t sb = smem_u32(smraw);
    const int tid  = threadIdx.x;
    const int lane = tid & 31;
    const int wid  = tid >> 5;          // 0..3, 32 q-rows each
    const int bh = blockIdx.y;
    const int b  = bh >> 4, h = bh & 15;
    const int s0 = blockIdx.x * 128;

    const size_t qoff = (size_t)(b * S + s0) * N3 + h * DK;
    const size_t koff = (size_t)b * S * N3 + D + h * DK;
    const size_t voff = koff + D;

    const uint32_t qb = sb;
    auto kstage = [&](int st) { return sb + FQPL + st * FKPL; };
    auto vstage = [&](int st) { return sb + FQPL + (2 + st) * FKPL; };

    auto cpQ = [&]() {
        #pragma unroll
        for (int p = 0; p < 8; p++) {
            int c = tid + (p << 7);
            int r = c >> 3, seg = c & 7;
            CP16(qb + (uint32_t)(r * FRB + seg * 16), Qp + qoff + (size_t)r * N3 + seg * 8);
        }
    };
    auto cpT1 = [&](size_t base, uint32_t dst) {
        #pragma unroll
        for (int p = 0; p < 4; p++) {
            int c = tid + (p << 7);
            int r = c >> 3, seg = c & 7;
            CP16(dst + (uint32_t)(r * FRB + seg * 16), Qp + base + (size_t)r * N3 + seg * 8);
        }
    };

    // init V pad columns (both stages, 64 rows): col 64 = 1.0h, cols 65..71 = 0
    #pragma unroll
    for (int p = 0; p < 4; p++) {
        int idx = tid + (p << 7);                // 0..511
        int stg = idx >> 8, rem = idx & 255;
        int r = rem >> 2, part = rem & 3;
        *reinterpret_cast<uint32_t*>(smraw + FQPL + (2 + stg) * FKPL + r * FRB + 128 + part * 4) =
            (part == 0) ? 0x00003C00u : 0u;
    }

    cpQ();
    cpT1(koff, kstage(0));
    CP_COMMIT();
    cpT1(voff, vstage(0));
    CP_COMMIT();

    const float k1 = 0.125f * 1.4426950408889634f;

    float mrow[2][2] = { {-1e30f, -1e30f}, {-1e30f, -1e30f} };
    float O[2][8][4], Oe[2][4];
    #pragma unroll
    for (int i = 0; i < 2; i++) {
        #pragma unroll
        for (int nj = 0; nj < 8; nj++)
            #pragma unroll
            for (int q = 0; q < 4; q++) O[i][nj][q] = 0.f;
        #pragma unroll
        for (int q = 0; q < 4; q++) Oe[i][q] = 0.f;
    }

    uint32_t Qf[4][2][4];                        // hoisted Q fragments [c][i][4]

    const int l8 = lane & 7, mt = lane >> 3;

    constexpr int NT = S / 64;                   // 16 tiles
    for (int t = 0; t < NT; t++) {
        const int st = t & 1;
        const uint32_t kst = kstage(st), vst = vstage(st);

        if (t + 1 < NT) {
            cpT1(koff + (size_t)(t + 1) * 64 * N3, kstage(st ^ 1));
            CP_COMMIT();
            CPWG(2);
        } else {
            CPWG(1);
        }
        __syncthreads();

        if (t == 0) {                            // Q resident now; load frags once
            #pragma unroll
            for (int c = 0; c < 4; c++)
                #pragma unroll
                for (int i = 0; i < 2; i++)
                    LDSM4(Qf[c][i], qb + (uint32_t)((wid * 32 + i * 16 + (lane & 15)) * FRB
                                                    + c * 32 + (lane >> 4) * 16));
        }

        // ---- S = Q K^T  (32 q-rows x 64 k-rows per warp) ----
        float Sr[2][8][4];
        #pragma unroll
        for (int i = 0; i < 2; i++)
            #pragma unroll
            for (int j = 0; j < 8; j++)
                #pragma unroll
                for (int q = 0; q < 4; q++) Sr[i][j][q] = 0.f;

        #pragma unroll
        for (int c = 0; c < 4; c++) {
            #pragma unroll
            for (int jj = 0; jj < 4; jj++) {
                uint32_t bd = kst + (uint32_t)((jj * 16 + (mt >> 1) * 8 + l8) * FRB
                                               + c * 32 + (mt & 1) * 16);
                uint32_t bh4[4];
                LDSM4(bh4, bd);
                #pragma unroll
                for (int i = 0; i < 2; i++) {
                    MMA16816(Sr[i][jj * 2],     Qf[c][i], bh4);
                    MMA16816(Sr[i][jj * 2 + 1], Qf[c][i], bh4 + 2);
                }
            }
        }

        if (t + 1 < NT) {
            cpT1(voff + (size_t)(t + 1) * 64 * N3, vstage(st ^ 1));
            CP_COMMIT();
        }

        // ---- scale + pre-scaled fp16 mask ----
        #pragma unroll
        for (int i = 0; i < 2; i++) {
            const __half* mA = maskh + (size_t)(s0 + wid * 32 + i * 16 + (lane >> 2)) * S + t * 64;
            const __half* mB = mA + 8 * S;
            #pragma unroll
            for (int j = 0; j < 8; j++) {
                int tc = j * 8 + (lane & 3) * 2;
                float2 ma = __half22float2(*reinterpret_cast<const __half2*>(mA + tc));
                float2 mb = __half22float2(*reinterpret_cast<const __half2*>(mB + tc));
                Sr[i][j][0] = Sr[i][j][0] * k1 + ma.x;
                Sr[i][j][1] = Sr[i][j][1] * k1 + ma.y;
                Sr[i][j][2] = Sr[i][j][2] * k1 + mb.x;
                Sr[i][j][3] = Sr[i][j][3] * k1 + mb.y;
            }
        }

        // ---- online max (log2 domain) ----
        float mn[2][2];
        #pragma unroll
        for (int i = 0; i < 2; i++) {
            float mt0 = -1e30f, mt1 = -1e30f;
            #pragma unroll
            for (int j = 0; j < 8; j++) {
                mt0 = fmaxf(mt0, fmaxf(Sr[i][j][0], Sr[i][j][1]));
                mt1 = fmaxf(mt1, fmaxf(Sr[i][j][2], Sr[i][j][3]));
            }
            mt0 = fmaxf(mt0, __shfl_xor_sync(~0u, mt0, 1));
            mt0 = fmaxf(mt0, __shfl_xor_sync(~0u, mt0, 2));
            mt1 = fmaxf(mt1, __shfl_xor_sync(~0u, mt1, 1));
            mt1 = fmaxf(mt1, __shfl_xor_sync(~0u, mt1, 2));
            mn[i][0] = fmaxf(mrow[i][0], mt0);
            mn[i][1] = fmaxf(mrow[i][1], mt1);
            float a0 = ex2f(mrow[i][0] - mn[i][0]);
            float a1 = ex2f(mrow[i][1] - mn[i][1]);
            mrow[i][0] = mn[i][0]; mrow[i][1] = mn[i][1];
            #pragma unroll
            for (int nj = 0; nj < 8; nj++) {
                O[i][nj][0] *= a0; O[i][nj][1] *= a0;
                O[i][nj][2] *= a1; O[i][nj][3] *= a1;
            }
            Oe[i][0] *= a0; Oe[i][1] *= a0; Oe[i][2] *= a1; Oe[i][3] *= a1;
        }

        if (t + 1 < NT) { CPWG(2); } else { CPWG(0); }
        __syncthreads();

        // ---- O += P V with JIT fp16 P conversion (+ones column row sums) ----
        #pragma unroll
        for (int c = 0; c < 4; c++) {
            uint32_t Ph[2][4];
            #pragma unroll
            for (int i = 0; i < 2; i++) {
                Ph[i][0] = cvt_ex2(Sr[i][2 * c][0] - mn[i][0], Sr[i][2 * c][1] - mn[i][0]);
                Ph[i][1] = cvt_ex2(Sr[i][2 * c][2] - mn[i][1], Sr[i][2 * c][3] - mn[i][1]);
                Ph[i][2] = cvt_ex2(Sr[i][2 * c + 1][0] - mn[i][0], Sr[i][2 * c + 1][1] - mn[i][0]);
                Ph[i][3] = cvt_ex2(Sr[i][2 * c + 1][2] - mn[i][1], Sr[i][2 * c + 1][3] - mn[i][1]);
            }
            #pragma unroll
            for (int njp = 0; njp < 4; njp++) {
                uint32_t bd = vst + (uint32_t)((c * 16 + ((lane >> 3) & 1) * 8 + l8) * FRB
                                               + (njp * 16 + (lane >> 4) * 8) * 2);
                uint32_t vh4[4];
                LDSM4T(vh4, bd);
                #pragma unroll
                for (int i = 0; i < 2; i++) {
                    MMA16816(O[i][njp * 2],     Ph[i], vh4);
                    MMA16816(O[i][njp * 2 + 1], Ph[i], vh4 + 2);
                }
            }
            uint32_t ve[2];
            LDSM2T(ve, vst + (uint32_t)((c * 16 + (lane & 15)) * FRB + 128));
            #pragma unroll
            for (int i = 0; i < 2; i++)
                MMA16816(Oe[i], Ph[i], ve);
        }
    }

    // ---- write CTX plane ----
    #pragma unroll
    for (int i = 0; i < 2; i++) {
        float l0v = __shfl_sync(~0u, Oe[i][0], lane & 28);
        float l1v = __shfl_sync(~0u, Oe[i][2], lane & 28);
        const float il0 = 1.f / l0v, il1 = 1.f / l1v;
        const int sg0 = b * S + s0 + wid * 32 + i * 16 + (lane >> 2);
        #pragma unroll
        for (int nj = 0; nj < 8; nj++) {
            int c = h * DK + nj * 8 + (lane & 3) * 2;
            *reinterpret_cast<uint32_t*>(Cp + (size_t)sg0 * D + c) =
                pack_h2(O[i][nj][0] * il0, O[i][nj][1] * il0);
            *reinterpret_cast<uint32_t*>(Cp + (size_t)(sg0 + 8) * D + c) =
                pack_h2(O[i][nj][2] * il1, O[i][nj][3] * il1);
        }
    }
}

// ---------------- LayerNorm (optional fp16 plane output) ----------------
__global__ __launch_bounds__(256) void layernorm_k(
    const float* __restrict__ in, const float* __restrict__ w,
    const float* __restrict__ bb, float* __restrict__ out,
    __half* __restrict__ oh)
{
    __shared__ float sh1[8], sh2[8], shb[2];
    size_t row = blockIdx.x;
    const float* x = in + row * D;
    int tid = threadIdx.x, lane = tid & 31, wp = tid >> 5;

    float4 v = *reinterpret_cast<const float4*>(x + tid * 4);
    float s = v.x + v.y + v.z + v.w;
    float q = v.x * v.x + v.y * v.y + v.z * v.z + v.w * v.w;
    #pragma unroll
    for (int o = 16; o; o >>= 1) { s += __shfl_down_sync(~0u, s, o); q += __shfl_down_sync(~0u, q, o); }
    if (!lane) { sh1[wp] = s; sh2[wp] = q; }
    __syncthreads();
    if (tid < 32) {
        s = (tid < 8) ? sh1[tid] : 0.f;
        q = (tid < 8) ? sh2[tid] : 0.f;
        #pragma unroll
        for (int o = 4; o; o >>= 1) { s += __shfl_down_sync(~0u, s, o); q += __shfl_down_sync(~0u, q, o); }
        if (!tid) {
            float mu = s * (1.f / D);
            shb[0] = mu;
            shb[1] = rsqrtf(q * (1.f / D) - mu * mu + 1e-5f);
        }
    }
    __syncthreads();
    float mu = shb[0], rs = shb[1];
    float4 wv = *reinterpret_cast<const float4*>(w  + tid * 4);
    float4 bv = *reinterpret_cast<const float4*>(bb + tid * 4);
    float4 o4;
    o4.x = (v.x - mu) * rs * wv.x + bv.x;
    o4.y = (v.y - mu) * rs * wv.y + bv.y;
    o4.z = (v.z - mu) * rs * wv.z + bv.z;
    o4.w = (v.w - mu) * rs * wv.w + bv.w;
    *reinterpret_cast<float4*>(out + row * D + tid * 4) = o4;
    if (oh) {
        *reinterpret_cast<uint2*>(oh + row * D + tid * 4) =
            make_uint2(pack_h2(o4.x, o4.y), pack_h2(o4.z, o4.w));
    }
}

// ---------------- launch ----------------
extern "C" void kernel_launch(void* const* d_in, const int* in_sizes, int n_in,
                              void* d_out, int out_size)
{
    const float* src  = (const float*)d_in[0];
    const float* mask = (const float*)d_in[1];
    const float* Wq   = (const float*)d_in[2];
    const float* bq   = (const float*)d_in[3];
    const float* Wk   = (const float*)d_in[4];
    const float* bk   = (const float*)d_in[5];
    const float* Wv   = (const float*)d_in[6];
    const float* bv   = (const float*)d_in[7];
    const float* Wo   = (const float*)d_in[8];
    const float* bo   = (const float*)d_in[9];
    const float* ln1w = (const float*)d_in[10];
    const float* ln1b = (const float*)d_in[11];
    const float* W1   = (const float*)d_in[12];
    const float* b1   = (const float*)d_in[13];
    const float* W2   = (const float*)d_in[14];
    const float* b2   = (const float*)d_in[15];
    const float* ln2w = (const float*)d_in[16];
    const float* ln2b = (const float*)d_in[17];
    float* out = (float*)d_out;

    float *pbqkv, *pY, *pX, *pZ;
    __half *pqw, *pow_, *p1w, *p2w;
    __half *psp, *pQp, *pcp, *pxp, *php, *pmh;
    cudaGetSymbolAddress((void**)&pbqkv, g_bqkv);
    cudaGetSymbolAddress((void**)&pY,    g_Y);
    cudaGetSymbolAddress((void**)&pX,    g_X);
    cudaGetSymbolAddress((void**)&pZ,    g_Z);
    cudaGetSymbolAddress((void**)&pqw,   g_qkv_w);
    cudaGetSymbolAddress((void**)&pow_,  g_wo_w);
    cudaGetSymbolAddress((void**)&p1w,   g_w1_w);
    cudaGetSymbolAddress((void**)&p2w,   g_w2_w);
    cudaGetSymbolAddress((void**)&psp,   g_src_p);
    cudaGetSymbolAddress((void**)&pQp,   g_q_p);
    cudaGetSymbolAddress((void**)&pcp,   g_ctx_p);
    cudaGetSymbolAddress((void**)&pxp,   g_x_p);
    cudaGetSymbolAddress((void**)&php,   g_hf_p);
    cudaGetSymbolAddress((void**)&pmh,   g_mask_h);

    cudaFuncSetAttribute(gemm_mma,   cudaFuncAttributeMaxDynamicSharedMemorySize, GEMM_DSMEM);
    cudaFuncSetAttribute(flash_attn, cudaFuncAttributeMaxDynamicSharedMemorySize, FA_DSMEM);

    // 1) unified prep (one launch)
    prep2_k<<<PB_BIAS, 256>>>(Wq, Wk, Wv, bq, bk, bv, Wo, W1, W2, src, mask);

    // 2) QKV plane = src @ Wqkv + bqkv
    gemm_mma<<<dim3(N3 / 256, M / 128), 512, GEMM_DSMEM>>>(
        psp, pqw, nullptr, pQp, pbqkv, nullptr, N3, D, 0);

    // 3) fused attention -> CTX plane
    flash_attn<<<dim3(S / 128, B * H), 128, FA_DSMEM>>>(pQp, pmh, pcp);

    // 4) Y = src + CTX @ Wo + bo
    gemm_mma<<<dim3(D / 256, M / 128), 512, GEMM_DSMEM>>>(
        pcp, pow_, pY, nullptr, bo, src, D, D, 0);

    // 5) X = LN1(Y)  (+ fp16 plane)
    layernorm_k<<<M, 256>>>(pY, ln1w, ln1b, pX, pxp);

    // 6) Hf plane = relu(X @ W1 + b1)
    gemm_mma<<<dim3(F / 256, M / 128), 512, GEMM_DSMEM>>>(
        pxp, p1w, nullptr, php, b1, nullptr, F, D, 1);

    // 7) Z = X + Hf @ W2 + b2
    gemm_mma<<<dim3(D / 256, M / 128), 512, GEMM_DSMEM>>>(
        php, p2w, pZ, nullptr, b2, pX, D, F, 0);

    // 8) out = LN2(Z)
    layernorm_k<<<M, 256>>>(pZ, ln2w, ln2b, out, nullptr);
}

// round 16
// speedup vs baseline: 1.0713x; 1.0238x over previous
#include <cuda_runtime.h>
#include <cuda_fp16.h>
#include <math_constants.h>
#include <cstdint>

// ---------------- problem constants ----------------
constexpr int B  = 8;
constexpr int S  = 1024;
constexpr int D  = 1024;
constexpr int H  = 16;
constexpr int DK = 64;
constexpr int F  = 4096;
constexpr int M  = B * S;        // 8192 rows
constexpr int N3 = 3 * D;        // 3072 (Q|K|V concat)

// ---------------- scratch (static device memory; no allocation) ----------------
__device__ __align__(128) float g_bqkv[N3];

// weight planes (K-major [N][K]) fp16
__device__ __align__(128) __half g_qkv_w[(size_t)N3 * D];
__device__ __align__(128) __half g_wo_w [(size_t)D * D];
__device__ __align__(128) __half g_w1_w [(size_t)F * D];
__device__ __align__(128) __half g_w2_w [(size_t)D * F];

// activation planes (row-major [M][K]) fp16
__device__ __align__(128) __half g_src_p[(size_t)M * D];
__device__ __align__(128) __half g_q_p  [(size_t)M * N3];   // Q|K|V
__device__ __align__(128) __half g_ctx_p[(size_t)M * D];
__device__ __align__(128) __half g_y_p  [(size_t)M * D];    // src + attn_out (fp16)
__device__ __align__(128) __half g_x_p  [(size_t)M * D];    // LN1 out (fp16)
__device__ __align__(128) __half g_hf_p [(size_t)M * F];
__device__ __align__(128) __half g_z_p  [(size_t)M * D];    // x + ffn (fp16)

// pre-scaled fp16 mask: clamp(-log2e*1e9*mask, -60000)
__device__ __align__(128) __half g_mask_h[(size_t)S * S];

// ---------------- PTX helpers ----------------
__device__ __forceinline__ uint32_t smem_u32(const void* p) {
    uint32_t a;
    asm("{ .reg .u64 t; cvta.to.shared.u64 t, %1; cvt.u32.u64 %0, t; }" : "=r"(a) : "l"(p));
    return a;
}
#define CP16(dst, src) \
    asm volatile("cp.async.cg.shared.global [%0], [%1], 16;" :: "r"(dst), "l"(src) : "memory")
#define CP_COMMIT() asm volatile("cp.async.commit_group;" ::: "memory")
#define CPWG(n)     asm volatile("cp.async.wait_group " #n ";" ::: "memory")

#define LDSM4(r, addr) \
    asm volatile("ldmatrix.sync.aligned.m8n8.x4.shared.b16 {%0, %1, %2, %3}, [%4];" \
        : "=r"((r)[0]), "=r"((r)[1]), "=r"((r)[2]), "=r"((r)[3]) : "r"(addr))
#define LDSM4T(r, addr) \
    asm volatile("ldmatrix.sync.aligned.m8n8.x4.trans.shared.b16 {%0, %1, %2, %3}, [%4];" \
        : "=r"((r)[0]), "=r"((r)[1]), "=r"((r)[2]), "=r"((r)[3]) : "r"(addr))
#define LDSM2T(r, addr) \
    asm volatile("ldmatrix.sync.aligned.m8n8.x2.trans.shared.b16 {%0, %1}, [%2];" \
        : "=r"((r)[0]), "=r"((r)[1]) : "r"(addr))

#define MMA16816(d, a, b) \
    asm volatile("mma.sync.aligned.m16n8k16.row.col.f32.f16.f16.f32 " \
        "{%0, %1, %2, %3}, {%4, %5, %6, %7}, {%8, %9}, {%0, %1, %2, %3};" \
        : "+f"((d)[0]), "+f"((d)[1]), "+f"((d)[2]), "+f"((d)[3]) \
        : "r"((a)[0]), "r"((a)[1]), "r"((a)[2]), "r"((a)[3]), "r"((b)[0]), "r"((b)[1]))

__device__ __forceinline__ uint32_t pack_h2(float x, float y) {
    __half2 h; h.x = __float2half_rn(x); h.y = __float2half_rn(y);
    return *reinterpret_cast<uint32_t*>(&h);
}
__device__ __forceinline__ uint32_t cvt_ex2(float x, float y) {
    uint32_t p;
    asm("cvt.rn.f16x2.f32 %0, %2, %1;" : "=r"(p) : "f"(x), "f"(y));  // hi=y, lo=x
    asm("ex2.approx.f16x2 %0, %0;" : "+r"(p));
    return p;
}
__device__ __forceinline__ float ex2f(float x) {
    float d; asm("ex2.approx.f32 %0, %1;" : "=f"(d) : "f"(x)); return d;
}

// ---------------- unified prep: all conversions in ONE launch ----------------
__device__ __forceinline__ void convW_body(
    const float* __restrict__ W, __half* __restrict__ oh,
    int Kk, int Nn, int bx, int by, int tid, float (*t)[33])
{
    int n0 = bx * 32, k0 = by * 32;
    int tx = tid & 31, ty = tid >> 5;
    #pragma unroll
    for (int i = 0; i < 4; i++)
        t[ty + i * 8][tx] = W[(size_t)(k0 + ty + i * 8) * Nn + n0 + tx];
    __syncthreads();
    #pragma unroll
    for (int i = 0; i < 4; i++) {
        int n = n0 + ty + i * 8;
        oh[(size_t)n * Kk + k0 + tx] = __float2half_rn(t[tx][ty + i * 8]);
    }
}

// direct Wq/Wk/Wv [H][D][DK] -> g_qkv_w [N3][D] fp16 (one pass)
__device__ __forceinline__ void conv_qkv_body(
    const float* __restrict__ W, int m, int h, int dblk, int kblk,
    int tid, float (*t)[33])
{
    int d0 = dblk * 32, k0 = kblk * 32;
    int tx = tid & 31, ty = tid >> 5;
    #pragma unroll
    for (int i = 0; i < 4; i++)
        t[ty + i * 8][tx] = W[(size_t)h * D * DK + (size_t)(d0 + ty + i * 8) * DK + k0 + tx];
    __syncthreads();
    #pragma unroll
    for (int i = 0; i < 4; i++) {
        int n = m * D + h * DK + k0 + ty + i * 8;
        g_qkv_w[(size_t)n * D + d0 + tx] = __float2half_rn(t[tx][ty + i * 8]);
    }
}

constexpr int PB_QKV  = 3072;
constexpr int PB_WO   = PB_QKV  + 1024;
constexpr int PB_W1   = PB_WO   + 4096;
constexpr int PB_W2   = PB_W1   + 4096;
constexpr int PB_SRC  = PB_W2   + 8192;
constexpr int PB_MASK = PB_SRC  + 1024;
constexpr int PB_BIAS = PB_MASK + 12;

__global__ __launch_bounds__(256) void prep2_k(
    const float* __restrict__ Wq, const float* __restrict__ Wk, const float* __restrict__ Wv,
    const float* __restrict__ bq, const float* __restrict__ bk, const float* __restrict__ bv,
    const float* __restrict__ Wo, const float* __restrict__ W1, const float* __restrict__ W2,
    const float* __restrict__ src, const float* __restrict__ mask)
{
    __shared__ float t[32][33];
    int blk = blockIdx.x, tid = threadIdx.x;
    if (blk < PB_QKV) {
        int m = blk >> 10, r = blk & 1023;
        int h = r >> 6, r2 = r & 63;
        const float* W = (m == 0) ? Wq : (m == 1) ? Wk : Wv;
        conv_qkv_body(W, m, h, r2 >> 1, r2 & 1, tid, t);
    } else if (blk < PB_WO) {
        int r = blk - PB_QKV;
        convW_body(Wo, g_wo_w, D, D, r % 32, r / 32, tid, t);
    } else if (blk < PB_W1) {
        int r = blk - PB_WO;
        convW_body(W1, g_w1_w, D, F, r % 128, r / 128, tid, t);
    } else if (blk < PB_W2) {
        int r = blk - PB_W1;
        convW_body(W2, g_w2_w, F, D, r % 32, r / 32, tid, t);
    } else if (blk < PB_SRC) {
        size_t i = ((size_t)(blk - PB_W2) * 256 + tid) * 4;
        float4 v = *reinterpret_cast<const float4*>(src + i);
        *reinterpret_cast<uint2*>(g_src_p + i) =
            make_uint2(pack_h2(v.x, v.y), pack_h2(v.z, v.w));
    } else if (blk < PB_MASK) {
        size_t i = ((size_t)(blk - PB_SRC) * 256 + tid) * 4;
        float4 v = *reinterpret_cast<const float4*>(mask + i);
        const float kk = -1.4426950408889634e9f;
        float a = fmaxf(-60000.f, kk * v.x), b2 = fmaxf(-60000.f, kk * v.y);
        float c = fmaxf(-60000.f, kk * v.z), d = fmaxf(-60000.f, kk * v.w);
        *reinterpret_cast<uint2*>(g_mask_h + i) = make_uint2(pack_h2(a, b2), pack_h2(c, d));
    } else {
        int idx = (blk - PB_MASK) * 256 + tid;
        int m = idx >> 10, k = idx & 1023;
        const float* bb = (m == 0) ? bq : (m == 1) ? bk : bv;
        g_bqkv[idx] = bb[k];
    }
}

// ---------------- HMMA GEMM: 128x256x64 CTA tile, 512 threads, 16 warps x 32x64 ----------------
constexpr int GRH   = 72;
constexpr int GRB   = GRH * 2;            // 144 bytes/row
constexpr int APL   = 128 * GRB;          // 18432
constexpr int BPL   = 256 * GRB;          // 36864
constexpr int GSTG  = APL + BPL;          // 55296
constexpr int GEMM_DSMEM = 3 * GSTG;      // 165888

__global__ __launch_bounds__(512, 1) void gemm_mma(
    const __half* __restrict__ Ap, const __half* __restrict__ Bp,
    float* __restrict__ Cf, __half* __restrict__ Chp,
    const float* __restrict__ bias,
    const float* __restrict__ resid, const __half* __restrict__ residh,
    int Nn, int Kk, int relu)
{
    extern __shared__ char smraw[];
    const uint32_t sbase = smem_u32(smraw);
    const int tid  = threadIdx.x;
    const int lane = tid & 31;
    const int wid  = tid >> 5;            // 0..15
    const int wm   = wid & 3;             // 4 warps in M (32 rows each)
    const int wn   = wid >> 2;            // 4 warps in N (64 cols each)
    const int m0 = blockIdx.y * 128;
    const int n0 = blockIdx.x * 256;
    const int nk = Kk >> 6;

    float acc[2][8][4];
    #pragma unroll
    for (int i = 0; i < 2; i++)
        #pragma unroll
        for (int j = 0; j < 8; j++)
            #pragma unroll
            for (int q = 0; q < 4; q++) acc[i][j][q] = 0.f;

    auto load = [&](int ci, int stage) {
        const uint32_t sb = sbase + stage * GSTG;
        const int k0 = ci << 6;
        #pragma unroll
        for (int p = 0; p < 2; p++) {
            int c = tid + (p << 9);
            int r = c >> 3, seg = c & 7;
            CP16(sb + (uint32_t)(r * GRB + seg * 16),
                 Ap + (size_t)(m0 + r) * Kk + k0 + seg * 8);
        }
        #pragma unroll
        for (int p = 0; p < 4; p++) {
            int c = tid + (p << 9);
            int r = c >> 3, seg = c & 7;
            CP16(sb + APL + (uint32_t)(r * GRB + seg * 16),
                 Bp + (size_t)(n0 + r) * Kk + k0 + seg * 8);
        }
        CP_COMMIT();
    };

    const int l8 = lane & 7, mt = lane >> 3;

    auto compute = [&](int stage) {
        const uint32_t ab = sbase + stage * GSTG;
        const uint32_t bb = ab + APL;
        #pragma unroll
        for (int h = 0; h < 4; h++) {
            uint32_t Af[2][4];
            #pragma unroll
            for (int i = 0; i < 2; i++) {
                int r = wm * 32 + i * 16 + (lane & 15);
                LDSM4(Af[i], ab + (uint32_t)(r * GRB + h * 32 + (lane >> 4) * 16));
            }
            #pragma unroll
            for (int jt = 0; jt < 4; jt++) {
                int nr = wn * 64 + jt * 16 + (mt >> 1) * 8 + l8;
                uint32_t q[4];
                LDSM4(q, bb + (uint32_t)(nr * GRB + h * 32 + (mt & 1) * 16));
                #pragma unroll
                for (int i = 0; i < 2; i++) {
                    MMA16816(acc[i][jt * 2],     Af[i], q);
                    MMA16816(acc[i][jt * 2 + 1], Af[i], q + 2);
                }
            }
        }
    };

    load(0, 0);
    load(1, 1);

    for (int i = 0; i < nk; i++) {
        if (i + 1 < nk) { CPWG(1); } else { CPWG(0); }
        __syncthreads();
        if (i + 2 < nk) load(i + 2, (i + 2) % 3);
        compute(i % 3);
    }

    #pragma unroll
    for (int i = 0; i < 2; i++) {
        int r = m0 + wm * 32 + i * 16 + (lane >> 2);
        #pragma unroll
        for (int j = 0; j < 8; j++) {
            int c = n0 + wn * 64 + j * 8 + (lane & 3) * 2;
            float2 v0 = { acc[i][j][0], acc[i][j][1] };
            float2 v1 = { acc[i][j][2], acc[i][j][3] };
            float2 bv = *reinterpret_cast<const float2*>(bias + c);
            v0.x += bv.x; v0.y += bv.y;
            v1.x += bv.x; v1.y += bv.y;
            if (resid) {
                float2 r0 = *reinterpret_cast<const float2*>(resid + (size_t)r * Nn + c);
                float2 r1 = *reinterpret_cast<const float2*>(resid + (size_t)(r + 8) * Nn + c);
                v0.x += r0.x; v0.y += r0.y;
                v1.x += r1.x; v1.y += r1.y;
            }
            if (residh) {
                float2 r0 = __half22float2(*reinterpret_cast<const __half2*>(residh + (size_t)r * Nn + c));
                float2 r1 = __half22float2(*reinterpret_cast<const __half2*>(residh + (size_t)(r + 8) * Nn + c));
                v0.x += r0.x; v0.y += r0.y;
                v1.x += r1.x; v1.y += r1.y;
            }
            if (relu) {
                v0.x = fmaxf(v0.x, 0.f); v0.y = fmaxf(v0.y, 0.f);
                v1.x = fmaxf(v1.x, 0.f); v1.y = fmaxf(v1.y, 0.f);
            }
            if (Cf) {
                *reinterpret_cast<float2*>(Cf + (size_t)r * Nn + c) = v0;
                *reinterpret_cast<float2*>(Cf + (size_t)(r + 8) * Nn + c) = v1;
            }
            if (Chp) {
                *reinterpret_cast<uint32_t*>(Chp + (size_t)r * Nn + c) = pack_h2(v0.x, v0.y);
                *reinterpret_cast<uint32_t*>(Chp + (size_t)(r + 8) * Nn + c) = pack_h2(v1.x, v1.y);
            }
        }
    }
}

// ---------------- fused flash attention: 4 warps x 32 q-rows, 64-row K/V tiles ----------------
// Q fragments hoisted into registers (reused across all 16 K-tiles).
constexpr int FR   = 72;
constexpr int FRB  = FR * 2;          // 144 bytes
constexpr int FQPL = 128 * FRB;       // 18432
constexpr int FKPL = 64 * FRB;        // 9216
constexpr int FA_DSMEM = FQPL + 4 * FKPL;  // 55296

__global__ __launch_bounds__(128, 2) void flash_attn(
    const __half* __restrict__ Qp, const __half* __restrict__ maskh,
    __half* __restrict__ Cp)
{
    extern __shared__ char smraw[];
    const uint32_t sb = smem_u32(smraw);
    const int tid  = threadIdx.x;
    const int lane = tid & 31;
    const int wid  = tid >> 5;          // 0..3, 32 q-rows each
    const int bh = blockIdx.y;
    const int b  = bh >> 4, h = bh & 15;
    const int s0 = blockIdx.x * 128;

    const size_t qoff = (size_t)(b * S + s0) * N3 + h * DK;
    const size_t koff = (size_t)b * S * N3 + D + h * DK;
    const size_t voff = koff + D;

    const uint32_t qb = sb;
    auto kstage = [&](int st) { return sb + FQPL + st * FKPL; };
    auto vstage = [&](int st) { return sb + FQPL + (2 + st) * FKPL; };

    auto cpQ = [&]() {
        #pragma unroll
        for (int p = 0; p < 8; p++) {
            int c = tid + (p << 7);
            int r = c >> 3, seg = c & 7;
            CP16(qb + (uint32_t)(r * FRB + seg * 16), Qp + qoff + (size_t)r * N3 + seg * 8);
        }
    };
    auto cpT1 = [&](size_t base, uint32_t dst) {
        #pragma unroll
        for (int p = 0; p < 4; p++) {
            int c = tid + (p << 7);
            int r = c >> 3, seg = c & 7;
            CP16(dst + (uint32_t)(r * FRB + seg * 16), Qp + base + (size_t)r * N3 + seg * 8);
        }
    };

    // init V pad columns (both stages, 64 rows): col 64 = 1.0h, cols 65..71 = 0
    #pragma unroll
    for (int p = 0; p < 4; p++) {
        int idx = tid + (p << 7);                // 0..511
        int stg = idx >> 8, rem = idx & 255;
        int r = rem >> 2, part = rem & 3;
        *reinterpret_cast<uint32_t*>(smraw + FQPL + (2 + stg) * FKPL + r * FRB + 128 + part * 4) =
            (part == 0) ? 0x00003C00u : 0u;
    }

    cpQ();
    cpT1(koff, kstage(0));
    CP_COMMIT();
    cpT1(voff, vstage(0));
    CP_COMMIT();

    const float k1 = 0.125f * 1.4426950408889634f;

    float mrow[2][2] = { {-1e30f, -1e30f}, {-1e30f, -1e30f} };
    float O[2][8][4], Oe[2][4];
    #pragma unroll
    for (int i = 0; i < 2; i++) {
        #pragma unroll
        for (int nj = 0; nj < 8; nj++)
            #pragma unroll
            for (int q = 0; q < 4; q++) O[i][nj][q] = 0.f;
        #pragma unroll
        for (int q = 0; q < 4; q++) Oe[i][q] = 0.f;
    }

    uint32_t Qf[4][2][4];                        // hoisted Q fragments [c][i][4]

    const int l8 = lane & 7, mt = lane >> 3;

    constexpr int NT = S / 64;                   // 16 tiles
    for (int t = 0; t < NT; t++) {
        const int st = t & 1;
        const uint32_t kst = kstage(st), vst = vstage(st);

        if (t + 1 < NT) {
            cpT1(koff + (size_t)(t + 1) * 64 * N3, kstage(st ^ 1));
            CP_COMMIT();
            CPWG(2);
        } else {
            CPWG(1);
        }
        __syncthreads();

        if (t == 0) {
            #pragma unroll
            for (int c = 0; c < 4; c++)
                #pragma unroll
                for (int i = 0; i < 2; i++)
                    LDSM4(Qf[c][i], qb + (uint32_t)((wid * 32 + i * 16 + (lane & 15)) * FRB
                                                    + c * 32 + (lane >> 4) * 16));
        }

        // ---- S = Q K^T ----
        float Sr[2][8][4];
        #pragma unroll
        for (int i = 0; i < 2; i++)
            #pragma unroll
            for (int j = 0; j < 8; j++)
                #pragma unroll
                for (int q = 0; q < 4; q++) Sr[i][j][q] = 0.f;

        #pragma unroll
        for (int c = 0; c < 4; c++) {
            #pragma unroll
            for (int jj = 0; jj < 4; jj++) {
                uint32_t bd = kst + (uint32_t)((jj * 16 + (mt >> 1) * 8 + l8) * FRB
                                               + c * 32 + (mt & 1) * 16);
                uint32_t bh4[4];
                LDSM4(bh4, bd);
                #pragma unroll
                for (int i = 0; i < 2; i++) {
                    MMA16816(Sr[i][jj * 2],     Qf[c][i], bh4);
                    MMA16816(Sr[i][jj * 2 + 1], Qf[c][i], bh4 + 2);
                }
            }
        }

        if (t + 1 < NT) {
            cpT1(voff + (size_t)(t + 1) * 64 * N3, vstage(st ^ 1));
            CP_COMMIT();
        }

        // ---- scale + pre-scaled fp16 mask ----
        #pragma unroll
        for (int i = 0; i < 2; i++) {
            const __half* mA = maskh + (size_t)(s0 + wid * 32 + i * 16 + (lane >> 2)) * S + t * 64;
            const __half* mB = mA + 8 * S;
            #pragma unroll
            for (int j = 0; j < 8; j++) {
                int tc = j * 8 + (lane & 3) * 2;
                float2 ma = __half22float2(*reinterpret_cast<const __half2*>(mA + tc));
                float2 mb = __half22float2(*reinterpret_cast<const __half2*>(mB + tc));
                Sr[i][j][0] = Sr[i][j][0] * k1 + ma.x;
                Sr[i][j][1] = Sr[i][j][1] * k1 + ma.y;
                Sr[i][j][2] = Sr[i][j][2] * k1 + mb.x;
                Sr[i][j][3] = Sr[i][j][3] * k1 + mb.y;
            }
        }

        // ---- online max (log2 domain) ----
        float mn[2][2];
        #pragma unroll
        for (int i = 0; i < 2; i++) {
            float mt0 = -1e30f, mt1 = -1e30f;
            #pragma unroll
            for (int j = 0; j < 8; j++) {
                mt0 = fmaxf(mt0, fmaxf(Sr[i][j][0], Sr[i][j][1]));
                mt1 = fmaxf(mt1, fmaxf(Sr[i][j][2], Sr[i][j][3]));
            }
            mt0 = fmaxf(mt0, __shfl_xor_sync(~0u, mt0, 1));
            mt0 = fmaxf(mt0, __shfl_xor_sync(~0u, mt0, 2));
            mt1 = fmaxf(mt1, __shfl_xor_sync(~0u, mt1, 1));
            mt1 = fmaxf(mt1, __shfl_xor_sync(~0u, mt1, 2));
            mn[i][0] = fmaxf(mrow[i][0], mt0);
            mn[i][1] = fmaxf(mrow[i][1], mt1);
            float a0 = ex2f(mrow[i][0] - mn[i][0]);
            float a1 = ex2f(mrow[i][1] - mn[i][1]);
            mrow[i][0] = mn[i][0]; mrow[i][1] = mn[i][1];
            #pragma unroll
            for (int nj = 0; nj < 8; nj++) {
                O[i][nj][0] *= a0; O[i][nj][1] *= a0;
                O[i][nj][2] *= a1; O[i][nj][3] *= a1;
            }
            Oe[i][0] *= a0; Oe[i][1] *= a0; Oe[i][2] *= a1; Oe[i][3] *= a1;
        }

        if (t + 1 < NT) { CPWG(2); } else { CPWG(0); }
        __syncthreads();

        // ---- O += P V with JIT fp16 P conversion (+ones column row sums) ----
        #pragma unroll
        for (int c = 0; c < 4; c++) {
            uint32_t Ph[2][4];
            #pragma unroll
            for (int i = 0; i < 2; i++) {
                Ph[i][0] = cvt_ex2(Sr[i][2 * c][0] - mn[i][0], Sr[i][2 * c][1] - mn[i][0]);
                Ph[i][1] = cvt_ex2(Sr[i][2 * c][2] - mn[i][1], Sr[i][2 * c][3] - mn[i][1]);
                Ph[i][2] = cvt_ex2(Sr[i][2 * c + 1][0] - mn[i][0], Sr[i][2 * c + 1][1] - mn[i][0]);
                Ph[i][3] = cvt_ex2(Sr[i][2 * c + 1][2] - mn[i][1], Sr[i][2 * c + 1][3] - mn[i][1]);
            }
            #pragma unroll
            for (int njp = 0; njp < 4; njp++) {
                uint32_t bd = vst + (uint32_t)((c * 16 + ((lane >> 3) & 1) * 8 + l8) * FRB
                                               + (njp * 16 + (lane >> 4) * 8) * 2);
                uint32_t vh4[4];
                LDSM4T(vh4, bd);
                #pragma unroll
                for (int i = 0; i < 2; i++) {
                    MMA16816(O[i][njp * 2],     Ph[i], vh4);
                    MMA16816(O[i][njp * 2 + 1], Ph[i], vh4 + 2);
                }
            }
            uint32_t ve[2];
            LDSM2T(ve, vst + (uint32_t)((c * 16 + (lane & 15)) * FRB + 128));
            #pragma unroll
            for (int i = 0; i < 2; i++)
                MMA16816(Oe[i], Ph[i], ve);
        }
    }

    // ---- write CTX plane ----
    #pragma unroll
    for (int i = 0; i < 2; i++) {
        float l0v = __shfl_sync(~0u, Oe[i][0], lane & 28);
        float l1v = __shfl_sync(~0u, Oe[i][2], lane & 28);
        const float il0 = 1.f / l0v, il1 = 1.f / l1v;
        const int sg0 = b * S + s0 + wid * 32 + i * 16 + (lane >> 2);
        #pragma unroll
        for (int nj = 0; nj < 8; nj++) {
            int c = h * DK + nj * 8 + (lane & 3) * 2;
            *reinterpret_cast<uint32_t*>(Cp + (size_t)sg0 * D + c) =
                pack_h2(O[i][nj][0] * il0, O[i][nj][1] * il0);
            *reinterpret_cast<uint32_t*>(Cp + (size_t)(sg0 + 8) * D + c) =
                pack_h2(O[i][nj][2] * il1, O[i][nj][3] * il1);
        }
    }
}

// ---------------- LayerNorm: fp16 input, optional fp32 / fp16 outputs ----------------
__global__ __launch_bounds__(256) void layernorm_k(
    const __half* __restrict__ in, const float* __restrict__ w,
    const float* __restrict__ bb, float* __restrict__ out,
    __half* __restrict__ oh)
{
    __shared__ float sh1[8], sh2[8], shb[2];
    size_t row = blockIdx.x;
    int tid = threadIdx.x, lane = tid & 31, wp = tid >> 5;

    uint2 raw = *reinterpret_cast<const uint2*>(in + row * D + tid * 4);
    float2 p01 = __half22float2(*reinterpret_cast<__half2*>(&raw.x));
    float2 p23 = __half22float2(*reinterpret_cast<__half2*>(&raw.y));
    float4 v = { p01.x, p01.y, p23.x, p23.y };

    float s = v.x + v.y + v.z + v.w;
    float q = v.x * v.x + v.y * v.y + v.z * v.z + v.w * v.w;
    #pragma unroll
    for (int o = 16; o; o >>= 1) { s += __shfl_down_sync(~0u, s, o); q += __shfl_down_sync(~0u, q, o); }
    if (!lane) { sh1[wp] = s; sh2[wp] = q; }
    __syncthreads();
    if (tid < 32) {
        s = (tid < 8) ? sh1[tid] : 0.f;
        q = (tid < 8) ? sh2[tid] : 0.f;
        #pragma unroll
        for (int o = 4; o; o >>= 1) { s += __shfl_down_sync(~0u, s, o); q += __shfl_down_sync(~0u, q, o); }
        if (!tid) {
            float mu = s * (1.f / D);
            shb[0] = mu;
            shb[1] = rsqrtf(q * (1.f / D) - mu * mu + 1e-5f);
        }
    }
    __syncthreads();
    float mu = shb[0], rs = shb[1];
    float4 wv = *reinterpret_cast<const float4*>(w  + tid * 4);
    float4 bv = *reinterpret_cast<const float4*>(bb + tid * 4);
    float4 o4;
    o4.x = (v.x - mu) * rs * wv.x + bv.x;
    o4.y = (v.y - mu) * rs * wv.y + bv.y;
    o4.z = (v.z - mu) * rs * wv.z + bv.z;
    o4.w = (v.w - mu) * rs * wv.w + bv.w;
    if (out)
        *reinterpret_cast<float4*>(out + row * D + tid * 4) = o4;
    if (oh)
        *reinterpret_cast<uint2*>(oh + row * D + tid * 4) =
            make_uint2(pack_h2(o4.x, o4.y), pack_h2(o4.z, o4.w));
}

// ---------------- launch ----------------
extern "C" void kernel_launch(void* const* d_in, const int* in_sizes, int n_in,
                              void* d_out, int out_size)
{
    const float* src  = (const float*)d_in[0];
    const float* mask = (const float*)d_in[1];
    const float* Wq   = (const float*)d_in[2];
    const float* bq   = (const float*)d_in[3];
    const float* Wk   = (const float*)d_in[4];
    const float* bk   = (const float*)d_in[5];
    const float* Wv   = (const float*)d_in[6];
    const float* bv   = (const float*)d_in[7];
    const float* Wo   = (const float*)d_in[8];
    const float* bo   = (const float*)d_in[9];
    const float* ln1w = (const float*)d_in[10];
    const float* ln1b = (const float*)d_in[11];
    const float* W1   = (const float*)d_in[12];
    const float* b1   = (const float*)d_in[13];
    const float* W2   = (const float*)d_in[14];
    const float* b2   = (const float*)d_in[15];
    const float* ln2w = (const float*)d_in[16];
    const float* ln2b = (const float*)d_in[17];
    float* out = (float*)d_out;

    float* pbqkv;
    __half *pqw, *pow_, *p1w, *p2w;
    __half *psp, *pQp, *pcp, *pyp, *pxp, *php, *pzp, *pmh;
    cudaGetSymbolAddress((void**)&pbqkv, g_bqkv);
    cudaGetSymbolAddress((void**)&pqw,   g_qkv_w);
    cudaGetSymbolAddress((void**)&pow_,  g_wo_w);
    cudaGetSymbolAddress((void**)&p1w,   g_w1_w);
    cudaGetSymbolAddress((void**)&p2w,   g_w2_w);
    cudaGetSymbolAddress((void**)&psp,   g_src_p);
    cudaGetSymbolAddress((void**)&pQp,   g_q_p);
    cudaGetSymbolAddress((void**)&pcp,   g_ctx_p);
    cudaGetSymbolAddress((void**)&pyp,   g_y_p);
    cudaGetSymbolAddress((void**)&pxp,   g_x_p);
    cudaGetSymbolAddress((void**)&php,   g_hf_p);
    cudaGetSymbolAddress((void**)&pzp,   g_z_p);
    cudaGetSymbolAddress((void**)&pmh,   g_mask_h);

    cudaFuncSetAttribute(gemm_mma,   cudaFuncAttributeMaxDynamicSharedMemorySize, GEMM_DSMEM);
    cudaFuncSetAttribute(flash_attn, cudaFuncAttributeMaxDynamicSharedMemorySize, FA_DSMEM);

    // 1) unified prep (one launch)
    prep2_k<<<PB_BIAS, 256>>>(Wq, Wk, Wv, bq, bk, bv, Wo, W1, W2, src, mask);

    // 2) QKV plane = src @ Wqkv + bqkv
    gemm_mma<<<dim3(N3 / 256, M / 128), 512, GEMM_DSMEM>>>(
        psp, pqw, nullptr, pQp, pbqkv, nullptr, nullptr, N3, D, 0);

    // 3) fused attention -> CTX plane
    flash_attn<<<dim3(S / 128, B * H), 128, FA_DSMEM>>>(pQp, pmh, pcp);

    // 4) Yh = src + CTX @ Wo + bo   (fp16 only)
    gemm_mma<<<dim3(D / 256, M / 128), 512, GEMM_DSMEM>>>(
        pcp, pow_, nullptr, pyp, bo, src, nullptr, D, D, 0);

    // 5) Xp = LN1(Yh)  (fp16 only)
    layernorm_k<<<M, 256>>>(pyp, ln1w, ln1b, nullptr, pxp);

    // 6) Hf plane = relu(X @ W1 + b1)
    gemm_mma<<<dim3(F / 256, M / 128), 512, GEMM_DSMEM>>>(
        pxp, p1w, nullptr, php, b1, nullptr, nullptr, F, D, 1);

    // 7) Zh = X + Hf @ W2 + b2   (fp16 only, fp16 residual)
    gemm_mma<<<dim3(D / 256, M / 128), 512, GEMM_DSMEM>>>(
        php, p2w, nullptr, pzp, b2, nullptr, pxp, D, F, 0);

    // 8) out = LN2(Zh)
    layernorm_k<<<M, 256>>>(pzp, ln2w, ln2b, out, nullptr);
}

// round 17
// speedup vs baseline: 1.0864x; 1.0141x over previous
#include <cuda_runtime.h>
#include <cuda_fp16.h>
#include <math_constants.h>
#include <cstdint>

// ---------------- problem constants ----------------
constexpr int B  = 8;
constexpr int S  = 1024;
constexpr int D  = 1024;
constexpr int H  = 16;
constexpr int DK = 64;
constexpr int F  = 4096;
constexpr int M  = B * S;        // 8192 rows
constexpr int N3 = 3 * D;        // 3072 (Q|K|V concat)

// ---------------- scratch (static device memory; no allocation) ----------------
__device__ __align__(128) float g_bqkv[N3];

// weight planes (K-major [N][K]) fp16
__device__ __align__(128) __half g_qkv_w[(size_t)N3 * D];
__device__ __align__(128) __half g_wo_w [(size_t)D * D];
__device__ __align__(128) __half g_w1_w [(size_t)F * D];
__device__ __align__(128) __half g_w2_w [(size_t)D * F];

// activation planes (row-major [M][K]) fp16
__device__ __align__(128) __half g_src_p[(size_t)M * D];
__device__ __align__(128) __half g_q_p  [(size_t)M * N3];   // Q|K|V
__device__ __align__(128) __half g_ctx_p[(size_t)M * D];
__device__ __align__(128) __half g_y_p  [(size_t)M * D];    // src + attn_out (fp16)
__device__ __align__(128) __half g_x_p  [(size_t)M * D];    // LN1 out (fp16)
__device__ __align__(128) __half g_hf_p [(size_t)M * F];
__device__ __align__(128) __half g_z_p  [(size_t)M * D];    // x + ffn (fp16)

// pre-scaled fp16 mask: clamp(-log2e*1e9*mask, -60000)
__device__ __align__(128) __half g_mask_h[(size_t)S * S];

// ---------------- PTX helpers ----------------
__device__ __forceinline__ uint32_t smem_u32(const void* p) {
    uint32_t a;
    asm("{ .reg .u64 t; cvta.to.shared.u64 t, %1; cvt.u32.u64 %0, t; }" : "=r"(a) : "l"(p));
    return a;
}
#define CP16(dst, src) \
    asm volatile("cp.async.cg.shared.global [%0], [%1], 16;" :: "r"(dst), "l"(src) : "memory")
#define CP_COMMIT() asm volatile("cp.async.commit_group;" ::: "memory")
#define CPWG(n)     asm volatile("cp.async.wait_group " #n ";" ::: "memory")

#define LDSM4(r, addr) \
    asm volatile("ldmatrix.sync.aligned.m8n8.x4.shared.b16 {%0, %1, %2, %3}, [%4];" \
        : "=r"((r)[0]), "=r"((r)[1]), "=r"((r)[2]), "=r"((r)[3]) : "r"(addr))
#define LDSM4T(r, addr) \
    asm volatile("ldmatrix.sync.aligned.m8n8.x4.trans.shared.b16 {%0, %1, %2, %3}, [%4];" \
        : "=r"((r)[0]), "=r"((r)[1]), "=r"((r)[2]), "=r"((r)[3]) : "r"(addr))
#define LDSM2T(r, addr) \
    asm volatile("ldmatrix.sync.aligned.m8n8.x2.trans.shared.b16 {%0, %1}, [%2];" \
        : "=r"((r)[0]), "=r"((r)[1]) : "r"(addr))

#define MMA16816(d, a, b) \
    asm volatile("mma.sync.aligned.m16n8k16.row.col.f32.f16.f16.f32 " \
        "{%0, %1, %2, %3}, {%4, %5, %6, %7}, {%8, %9}, {%0, %1, %2, %3};" \
        : "+f"((d)[0]), "+f"((d)[1]), "+f"((d)[2]), "+f"((d)[3]) \
        : "r"((a)[0]), "r"((a)[1]), "r"((a)[2]), "r"((a)[3]), "r"((b)[0]), "r"((b)[1]))

__device__ __forceinline__ uint32_t pack_h2(float x, float y) {
    __half2 h; h.x = __float2half_rn(x); h.y = __float2half_rn(y);
    return *reinterpret_cast<uint32_t*>(&h);
}
__device__ __forceinline__ uint32_t cvt_ex2(float x, float y) {
    uint32_t p;
    asm("cvt.rn.f16x2.f32 %0, %2, %1;" : "=r"(p) : "f"(x), "f"(y));  // hi=y, lo=x
    asm("ex2.approx.f16x2 %0, %0;" : "+r"(p));
    return p;
}
__device__ __forceinline__ float ex2f(float x) {
    float d; asm("ex2.approx.f32 %0, %1;" : "=f"(d) : "f"(x)); return d;
}

// ---------------- unified prep: all conversions in ONE launch ----------------
__device__ __forceinline__ void convW_body(
    const float* __restrict__ W, __half* __restrict__ oh,
    int Kk, int Nn, int bx, int by, int tid, float (*t)[33])
{
    int n0 = bx * 32, k0 = by * 32;
    int tx = tid & 31, ty = tid >> 5;
    #pragma unroll
    for (int i = 0; i < 4; i++)
        t[ty + i * 8][tx] = W[(size_t)(k0 + ty + i * 8) * Nn + n0 + tx];
    __syncthreads();
    #pragma unroll
    for (int i = 0; i < 4; i++) {
        int n = n0 + ty + i * 8;
        oh[(size_t)n * Kk + k0 + tx] = __float2half_rn(t[tx][ty + i * 8]);
    }
}

// direct Wq/Wk/Wv [H][D][DK] -> g_qkv_w [N3][D] fp16 (one pass)
__device__ __forceinline__ void conv_qkv_body(
    const float* __restrict__ W, int m, int h, int dblk, int kblk,
    int tid, float (*t)[33])
{
    int d0 = dblk * 32, k0 = kblk * 32;
    int tx = tid & 31, ty = tid >> 5;
    #pragma unroll
    for (int i = 0; i < 4; i++)
        t[ty + i * 8][tx] = W[(size_t)h * D * DK + (size_t)(d0 + ty + i * 8) * DK + k0 + tx];
    __syncthreads();
    #pragma unroll
    for (int i = 0; i < 4; i++) {
        int n = m * D + h * DK + k0 + ty + i * 8;
        g_qkv_w[(size_t)n * D + d0 + tx] = __float2half_rn(t[tx][ty + i * 8]);
    }
}

constexpr int PB_QKV  = 3072;
constexpr int PB_WO   = PB_QKV  + 1024;
constexpr int PB_W1   = PB_WO   + 4096;
constexpr int PB_W2   = PB_W1   + 4096;
constexpr int PB_SRC  = PB_W2   + 8192;
constexpr int PB_MASK = PB_SRC  + 1024;
constexpr int PB_BIAS = PB_MASK + 12;

__global__ __launch_bounds__(256) void prep2_k(
    const float* __restrict__ Wq, const float* __restrict__ Wk, const float* __restrict__ Wv,
    const float* __restrict__ bq, const float* __restrict__ bk, const float* __restrict__ bv,
    const float* __restrict__ Wo, const float* __restrict__ W1, const float* __restrict__ W2,
    const float* __restrict__ src, const float* __restrict__ mask)
{
    __shared__ float t[32][33];
    int blk = blockIdx.x, tid = threadIdx.x;
    if (blk < PB_QKV) {
        int m = blk >> 10, r = blk & 1023;
        int h = r >> 6, r2 = r & 63;
        const float* W = (m == 0) ? Wq : (m == 1) ? Wk : Wv;
        conv_qkv_body(W, m, h, r2 >> 1, r2 & 1, tid, t);
    } else if (blk < PB_WO) {
        int r = blk - PB_QKV;
        convW_body(Wo, g_wo_w, D, D, r % 32, r / 32, tid, t);
    } else if (blk < PB_W1) {
        int r = blk - PB_WO;
        convW_body(W1, g_w1_w, D, F, r % 128, r / 128, tid, t);
    } else if (blk < PB_W2) {
        int r = blk - PB_W1;
        convW_body(W2, g_w2_w, F, D, r % 32, r / 32, tid, t);
    } else if (blk < PB_SRC) {
        size_t i = ((size_t)(blk - PB_W2) * 256 + tid) * 4;
        float4 v = *reinterpret_cast<const float4*>(src + i);
        *reinterpret_cast<uint2*>(g_src_p + i) =
            make_uint2(pack_h2(v.x, v.y), pack_h2(v.z, v.w));
    } else if (blk < PB_MASK) {
        size_t i = ((size_t)(blk - PB_SRC) * 256 + tid) * 4;
        float4 v = *reinterpret_cast<const float4*>(mask + i);
        const float kk = -1.4426950408889634e9f;
        float a = fmaxf(-60000.f, kk * v.x), b2 = fmaxf(-60000.f, kk * v.y);
        float c = fmaxf(-60000.f, kk * v.z), d = fmaxf(-60000.f, kk * v.w);
        *reinterpret_cast<uint2*>(g_mask_h + i) = make_uint2(pack_h2(a, b2), pack_h2(c, d));
    } else {
        int idx = (blk - PB_MASK) * 256 + tid;
        int m = idx >> 10, k = idx & 1023;
        const float* bb = (m == 0) ? bq : (m == 1) ? bk : bv;
        g_bqkv[idx] = bb[k];
    }
}

// ---------------- HMMA GEMM: 128x256x64 CTA tile, 512 threads, 4-stage cp.async ----------------
constexpr int GRH   = 72;
constexpr int GRB   = GRH * 2;            // 144 bytes/row
constexpr int APL   = 128 * GRB;          // 18432
constexpr int BPL   = 256 * GRB;          // 36864
constexpr int GSTG  = APL + BPL;          // 55296
constexpr int GEMM_DSMEM = 4 * GSTG;      // 221184

__global__ __launch_bounds__(512, 1) void gemm_mma(
    const __half* __restrict__ Ap, const __half* __restrict__ Bp,
    float* __restrict__ Cf, __half* __restrict__ Chp,
    const float* __restrict__ bias,
    const float* __restrict__ resid, const __half* __restrict__ residh,
    int Nn, int Kk, int relu)
{
    extern __shared__ char smraw[];
    const uint32_t sbase = smem_u32(smraw);
    const int tid  = threadIdx.x;
    const int lane = tid & 31;
    const int wid  = tid >> 5;            // 0..15
    const int wm   = wid & 3;             // 4 warps in M (32 rows each)
    const int wn   = wid >> 2;            // 4 warps in N (64 cols each)
    const int m0 = blockIdx.y * 128;
    const int n0 = blockIdx.x * 256;
    const int nk = Kk >> 6;

    float acc[2][8][4];
    #pragma unroll
    for (int i = 0; i < 2; i++)
        #pragma unroll
        for (int j = 0; j < 8; j++)
            #pragma unroll
            for (int q = 0; q < 4; q++) acc[i][j][q] = 0.f;

    auto load = [&](int ci, int stage) {
        const uint32_t sb = sbase + stage * GSTG;
        const int k0 = ci << 6;
        #pragma unroll
        for (int p = 0; p < 2; p++) {
            int c = tid + (p << 9);
            int r = c >> 3, seg = c & 7;
            CP16(sb + (uint32_t)(r * GRB + seg * 16),
                 Ap + (size_t)(m0 + r) * Kk + k0 + seg * 8);
        }
        #pragma unroll
        for (int p = 0; p < 4; p++) {
            int c = tid + (p << 9);
            int r = c >> 3, seg = c & 7;
            CP16(sb + APL + (uint32_t)(r * GRB + seg * 16),
                 Bp + (size_t)(n0 + r) * Kk + k0 + seg * 8);
        }
        CP_COMMIT();
    };

    const int l8 = lane & 7, mt = lane >> 3;

    auto compute = [&](int stage) {
        const uint32_t ab = sbase + stage * GSTG;
        const uint32_t bb = ab + APL;
        #pragma unroll
        for (int h = 0; h < 4; h++) {
            uint32_t Af[2][4];
            #pragma unroll
            for (int i = 0; i < 2; i++) {
                int r = wm * 32 + i * 16 + (lane & 15);
                LDSM4(Af[i], ab + (uint32_t)(r * GRB + h * 32 + (lane >> 4) * 16));
            }
            #pragma unroll
            for (int jt = 0; jt < 4; jt++) {
                int nr = wn * 64 + jt * 16 + (mt >> 1) * 8 + l8;
                uint32_t q[4];
                LDSM4(q, bb + (uint32_t)(nr * GRB + h * 32 + (mt & 1) * 16));
                #pragma unroll
                for (int i = 0; i < 2; i++) {
                    MMA16816(acc[i][jt * 2],     Af[i], q);
                    MMA16816(acc[i][jt * 2 + 1], Af[i], q + 2);
                }
            }
        }
    };

    // 4-stage prologue
    load(0, 0);
    if (nk > 1) load(1, 1);
    if (nk > 2) load(2, 2);

    for (int i = 0; i < nk; i++) {
        if (i + 2 < nk)      { CPWG(2); }   // stages i+1, i+2 still pending
        else if (i + 1 < nk) { CPWG(1); }
        else                 { CPWG(0); }
        __syncthreads();
        if (i + 3 < nk) load(i + 3, (i + 3) & 3);
        compute(i & 3);
    }

    #pragma unroll
    for (int i = 0; i < 2; i++) {
        int r = m0 + wm * 32 + i * 16 + (lane >> 2);
        #pragma unroll
        for (int j = 0; j < 8; j++) {
            int c = n0 + wn * 64 + j * 8 + (lane & 3) * 2;
            float2 v0 = { acc[i][j][0], acc[i][j][1] };
            float2 v1 = { acc[i][j][2], acc[i][j][3] };
            float2 bv = *reinterpret_cast<const float2*>(bias + c);
            v0.x += bv.x; v0.y += bv.y;
            v1.x += bv.x; v1.y += bv.y;
            if (resid) {
                float2 r0 = *reinterpret_cast<const float2*>(resid + (size_t)r * Nn + c);
                float2 r1 = *reinterpret_cast<const float2*>(resid + (size_t)(r + 8) * Nn + c);
                v0.x += r0.x; v0.y += r0.y;
                v1.x += r1.x; v1.y += r1.y;
            }
            if (residh) {
                float2 r0 = __half22float2(*reinterpret_cast<const __half2*>(residh + (size_t)r * Nn + c));
                float2 r1 = __half22float2(*reinterpret_cast<const __half2*>(residh + (size_t)(r + 8) * Nn + c));
                v0.x += r0.x; v0.y += r0.y;
                v1.x += r1.x; v1.y += r1.y;
            }
            if (relu) {
                v0.x = fmaxf(v0.x, 0.f); v0.y = fmaxf(v0.y, 0.f);
                v1.x = fmaxf(v1.x, 0.f); v1.y = fmaxf(v1.y, 0.f);
            }
            if (Cf) {
                *reinterpret_cast<float2*>(Cf + (size_t)r * Nn + c) = v0;
                *reinterpret_cast<float2*>(Cf + (size_t)(r + 8) * Nn + c) = v1;
            }
            if (Chp) {
                *reinterpret_cast<uint32_t*>(Chp + (size_t)r * Nn + c) = pack_h2(v0.x, v0.y);
                *reinterpret_cast<uint32_t*>(Chp + (size_t)(r + 8) * Nn + c) = pack_h2(v1.x, v1.y);
            }
        }
    }
}

// ---------------- fused flash attention: 4 warps x 32 q-rows, 64-row K/V tiles ----------------
constexpr int FR   = 72;
constexpr int FRB  = FR * 2;          // 144 bytes
constexpr int FQPL = 128 * FRB;       // 18432
constexpr int FKPL = 64 * FRB;        // 9216
constexpr int FA_DSMEM = FQPL + 4 * FKPL;  // 55296

__global__ __launch_bounds__(128, 2) void flash_attn(
    const __half* __restrict__ Qp, const __half* __restrict__ maskh,
    __half* __restrict__ Cp)
{
    extern __shared__ char smraw[];
    const uint32_t sb = smem_u32(smraw);
    const int tid  = threadIdx.x;
    const int lane = tid & 31;
    const int wid  = tid >> 5;          // 0..3, 32 q-rows each
    const int bh = blockIdx.y;
    const int b  = bh >> 4, h = bh & 15;
    const int s0 = blockIdx.x * 128;

    const size_t qoff = (size_t)(b * S + s0) * N3 + h * DK;
    const size_t koff = (size_t)b * S * N3 + D + h * DK;
    const size_t voff = koff + D;

    const uint32_t qb = sb;
    auto kstage = [&](int st) { return sb + FQPL + st * FKPL; };
    auto vstage = [&](int st) { return sb + FQPL + (2 + st) * FKPL; };

    auto cpQ = [&]() {
        #pragma unroll
        for (int p = 0; p < 8; p++) {
            int c = tid + (p << 7);
            int r = c >> 3, seg = c & 7;
            CP16(qb + (uint32_t)(r * FRB + seg * 16), Qp + qoff + (size_t)r * N3 + seg * 8);
        }
    };
    auto cpT1 = [&](size_t base, uint32_t dst) {
        #pragma unroll
        for (int p = 0; p < 4; p++) {
            int c = tid + (p << 7);
            int r = c >> 3, seg = c & 7;
            CP16(dst + (uint32_t)(r * FRB + seg * 16), Qp + base + (size_t)r * N3 + seg * 8);
        }
    };

    // init V pad columns (both stages, 64 rows): col 64 = 1.0h, cols 65..71 = 0
    #pragma unroll
    for (int p = 0; p < 4; p++) {
        int idx = tid + (p << 7);                // 0..511
        int stg = idx >> 8, rem = idx & 255;
        int r = rem >> 2, part = rem & 3;
        *reinterpret_cast<uint32_t*>(smraw + FQPL + (2 + stg) * FKPL + r * FRB + 128 + part * 4) =
            (part == 0) ? 0x00003C00u : 0u;
    }

    cpQ();
    cpT1(koff, kstage(0));
    CP_COMMIT();
    cpT1(voff, vstage(0));
    CP_COMMIT();

    const float k1 = 0.125f * 1.4426950408889634f;

    float mrow[2][2] = { {-1e30f, -1e30f}, {-1e30f, -1e30f} };
    float O[2][8][4], Oe[2][4];
    #pragma unroll
    for (int i = 0; i < 2; i++) {
        #pragma unroll
        for (int nj = 0; nj < 8; nj++)
            #pragma unroll
            for (int q = 0; q < 4; q++) O[i][nj][q] = 0.f;
        #pragma unroll
        for (int q = 0; q < 4; q++) Oe[i][q] = 0.f;
    }

    uint32_t Qf[4][2][4];                        // hoisted Q fragments [c][i][4]

    const int l8 = lane & 7, mt = lane >> 3;

    constexpr int NT = S / 64;                   // 16 tiles
    for (int t = 0; t < NT; t++) {
        const int st = t & 1;
        const uint32_t kst = kstage(st), vst = vstage(st);

        if (t + 1 < NT) {
            cpT1(koff + (size_t)(t + 1) * 64 * N3, kstage(st ^ 1));
            CP_COMMIT();
            CPWG(2);
        } else {
            CPWG(1);
        }
        __syncthreads();

        if (t == 0) {
            #pragma unroll
            for (int c = 0; c < 4; c++)
                #pragma unroll
                for (int i = 0; i < 2; i++)
                    LDSM4(Qf[c][i], qb + (uint32_t)((wid * 32 + i * 16 + (lane & 15)) * FRB
                                                    + c * 32 + (lane >> 4) * 16));
        }

        // ---- S = Q K^T ----
        float Sr[2][8][4];
        #pragma unroll
        for (int i = 0; i < 2; i++)
            #pragma unroll
            for (int j = 0; j < 8; j++)
                #pragma unroll
                for (int q = 0; q < 4; q++) Sr[i][j][q] = 0.f;

        #pragma unroll
        for (int c = 0; c < 4; c++) {
            #pragma unroll
            for (int jj = 0; jj < 4; jj++) {
                uint32_t bd = kst + (uint32_t)((jj * 16 + (mt >> 1) * 8 + l8) * FRB
                                               + c * 32 + (mt & 1) * 16);
                uint32_t bh4[4];
                LDSM4(bh4, bd);
                #pragma unroll
                for (int i = 0; i < 2; i++) {
                    MMA16816(Sr[i][jj * 2],     Qf[c][i], bh4);
                    MMA16816(Sr[i][jj * 2 + 1], Qf[c][i], bh4 + 2);
                }
            }
        }

        if (t + 1 < NT) {
            cpT1(voff + (size_t)(t + 1) * 64 * N3, vstage(st ^ 1));
            CP_COMMIT();
        }

        // ---- scale + pre-scaled fp16 mask ----
        #pragma unroll
        for (int i = 0; i < 2; i++) {
            const __half* mA = maskh + (size_t)(s0 + wid * 32 + i * 16 + (lane >> 2)) * S + t * 64;
            const __half* mB = mA + 8 * S;
            #pragma unroll
            for (int j = 0; j < 8; j++) {
                int tc = j * 8 + (lane & 3) * 2;
                float2 ma = __half22float2(*reinterpret_cast<const __half2*>(mA + tc));
                float2 mb = __half22float2(*reinterpret_cast<const __half2*>(mB + tc));
                Sr[i][j][0] = Sr[i][j][0] * k1 + ma.x;
                Sr[i][j][1] = Sr[i][j][1] * k1 + ma.y;
                Sr[i][j][2] = Sr[i][j][2] * k1 + mb.x;
                Sr[i][j][3] = Sr[i][j][3] * k1 + mb.y;
            }
        }

        // ---- online max (log2 domain) ----
        float mn[2][2];
        #pragma unroll
        for (int i = 0; i < 2; i++) {
            float mt0 = -1e30f, mt1 = -1e30f;
            #pragma unroll
            for (int j = 0; j < 8; j++) {
                mt0 = fmaxf(mt0, fmaxf(Sr[i][j][0], Sr[i][j][1]));
                mt1 = fmaxf(mt1, fmaxf(Sr[i][j][2], Sr[i][j][3]));
            }
            mt0 = fmaxf(mt0, __shfl_xor_sync(~0u, mt0, 1));
            mt0 = fmaxf(mt0, __shfl_xor_sync(~0u, mt0, 2));
            mt1 = fmaxf(mt1, __shfl_xor_sync(~0u, mt1, 1));
            mt1 = fmaxf(mt1, __shfl_xor_sync(~0u, mt1, 2));
            mn[i][0] = fmaxf(mrow[i][0], mt0);
            mn[i][1] = fmaxf(mrow[i][1], mt1);
            float a0 = ex2f(mrow[i][0] - mn[i][0]);
            float a1 = ex2f(mrow[i][1] - mn[i][1]);
            mrow[i][0] = mn[i][0]; mrow[i][1] = mn[i][1];
            #pragma unroll
            for (int nj = 0; nj < 8; nj++) {
                O[i][nj][0] *= a0; O[i][nj][1] *= a0;
                O[i][nj][2] *= a1; O[i][nj][3] *= a1;
            }
            Oe[i][0] *= a0; Oe[i][1] *= a0; Oe[i][2] *= a1; Oe[i][3] *= a1;
        }

        if (t + 1 < NT) { CPWG(2); } else { CPWG(0); }
        __syncthreads();

        // ---- O += P V with JIT fp16 P conversion (+ones column row sums) ----
        #pragma unroll
        for (int c = 0; c < 4; c++) {
            uint32_t Ph[2][4];
            #pragma unroll
            for (int i = 0; i < 2; i++) {
                Ph[i][0] = cvt_ex2(Sr[i][2 * c][0] - mn[i][0], Sr[i][2 * c][1] - mn[i][0]);
                Ph[i][1] = cvt_ex2(Sr[i][2 * c][2] - mn[i][1], Sr[i][2 * c][3] - mn[i][1]);
                Ph[i][2] = cvt_ex2(Sr[i][2 * c + 1][0] - mn[i][0], Sr[i][2 * c + 1][1] - mn[i][0]);
                Ph[i][3] = cvt_ex2(Sr[i][2 * c + 1][2] - mn[i][1], Sr[i][2 * c + 1][3] - mn[i][1]);
            }
            #pragma unroll
            for (int njp = 0; njp < 4; njp++) {
                uint32_t bd = vst + (uint32_t)((c * 16 + ((lane >> 3) & 1) * 8 + l8) * FRB
                                               + (njp * 16 + (lane >> 4) * 8) * 2);
                uint32_t vh4[4];
                LDSM4T(vh4, bd);
                #pragma unroll
                for (int i = 0; i < 2; i++) {
                    MMA16816(O[i][njp * 2],     Ph[i], vh4);
                    MMA16816(O[i][njp * 2 + 1], Ph[i], vh4 + 2);
                }
            }
            uint32_t ve[2];
            LDSM2T(ve, vst + (uint32_t)((c * 16 + (lane & 15)) * FRB + 128));
            #pragma unroll
            for (int i = 0; i < 2; i++)
                MMA16816(Oe[i], Ph[i], ve);
        }
    }

    // ---- write CTX plane ----
    #pragma unroll
    for (int i = 0; i < 2; i++) {
        float l0v = __shfl_sync(~0u, Oe[i][0], lane & 28);
        float l1v = __shfl_sync(~0u, Oe[i][2], lane & 28);
        const float il0 = 1.f / l0v, il1 = 1.f / l1v;
        const int sg0 = b * S + s0 + wid * 32 + i * 16 + (lane >> 2);
        #pragma unroll
        for (int nj = 0; nj < 8; nj++) {
            int c = h * DK + nj * 8 + (lane & 3) * 2;
            *reinterpret_cast<uint32_t*>(Cp + (size_t)sg0 * D + c) =
                pack_h2(O[i][nj][0] * il0, O[i][nj][1] * il0);
            *reinterpret_cast<uint32_t*>(Cp + (size_t)(sg0 + 8) * D + c) =
                pack_h2(O[i][nj][2] * il1, O[i][nj][3] * il1);
        }
    }
}

// ---------------- LayerNorm: fp16 input, optional fp32 / fp16 outputs ----------------
__global__ __launch_bounds__(256) void layernorm_k(
    const __half* __restrict__ in, const float* __restrict__ w,
    const float* __restrict__ bb, float* __restrict__ out,
    __half* __restrict__ oh)
{
    __shared__ float sh1[8], sh2[8], shb[2];
    size_t row = blockIdx.x;
    int tid = threadIdx.x, lane = tid & 31, wp = tid >> 5;

    uint2 raw = *reinterpret_cast<const uint2*>(in + row * D + tid * 4);
    float2 p01 = __half22float2(*reinterpret_cast<__half2*>(&raw.x));
    float2 p23 = __half22float2(*reinterpret_cast<__half2*>(&raw.y));
    float4 v = { p01.x, p01.y, p23.x, p23.y };

    float s = v.x + v.y + v.z + v.w;
    float q = v.x * v.x + v.y * v.y + v.z * v.z + v.w * v.w;
    #pragma unroll
    for (int o = 16; o; o >>= 1) { s += __shfl_down_sync(~0u, s, o); q += __shfl_down_sync(~0u, q, o); }
    if (!lane) { sh1[wp] = s; sh2[wp] = q; }
    __syncthreads();
    if (tid < 32) {
        s = (tid < 8) ? sh1[tid] : 0.f;
        q = (tid < 8) ? sh2[tid] : 0.f;
        #pragma unroll
        for (int o = 4; o; o >>= 1) { s += __shfl_down_sync(~0u, s, o); q += __shfl_down_sync(~0u, q, o); }
        if (!tid) {
            float mu = s * (1.f / D);
            shb[0] = mu;
            shb[1] = rsqrtf(q * (1.f / D) - mu * mu + 1e-5f);
        }
    }
    __syncthreads();
    float mu = shb[0], rs = shb[1];
    float4 wv = *reinterpret_cast<const float4*>(w  + tid * 4);
    float4 bv = *reinterpret_cast<const float4*>(bb + tid * 4);
    float4 o4;
    o4.x = (v.x - mu) * rs * wv.x + bv.x;
    o4.y = (v.y - mu) * rs * wv.y + bv.y;
    o4.z = (v.z - mu) * rs * wv.z + bv.z;
    o4.w = (v.w - mu) * rs * wv.w + bv.w;
    if (out)
        *reinterpret_cast<float4*>(out + row * D + tid * 4) = o4;
    if (oh)
        *reinterpret_cast<uint2*>(oh + row * D + tid * 4) =
            make_uint2(pack_h2(o4.x, o4.y), pack_h2(o4.z, o4.w));
}

// ---------------- launch ----------------
extern "C" void kernel_launch(void* const* d_in, const int* in_sizes, int n_in,
                              void* d_out, int out_size)
{
    const float* src  = (const float*)d_in[0];
    const float* mask = (const float*)d_in[1];
    const float* Wq   = (const float*)d_in[2];
    const float* bq   = (const float*)d_in[3];
    const float* Wk   = (const float*)d_in[4];
    const float* bk   = (const float*)d_in[5];
    const float* Wv   = (const float*)d_in[6];
    const float* bv   = (const float*)d_in[7];
    const float* Wo   = (const float*)d_in[8];
    const float* bo   = (const float*)d_in[9];
    const float* ln1w = (const float*)d_in[10];
    const float* ln1b = (const float*)d_in[11];
    const float* W1   = (const float*)d_in[12];
    const float* b1   = (const float*)d_in[13];
    const float* W2   = (const float*)d_in[14];
    const float* b2   = (const float*)d_in[15];
    const float* ln2w = (const float*)d_in[16];
    const float* ln2b = (const float*)d_in[17];
    float* out = (float*)d_out;

    float* pbqkv;
    __half *pqw, *pow_, *p1w, *p2w;
    __half *psp, *pQp, *pcp, *pyp, *pxp, *php, *pzp, *pmh;
    cudaGetSymbolAddress((void**)&pbqkv, g_bqkv);
    cudaGetSymbolAddress((void**)&pqw,   g_qkv_w);
    cudaGetSymbolAddress((void**)&pow_,  g_wo_w);
    cudaGetSymbolAddress((void**)&p1w,   g_w1_w);
    cudaGetSymbolAddress((void**)&p2w,   g_w2_w);
    cudaGetSymbolAddress((void**)&psp,   g_src_p);
    cudaGetSymbolAddress((void**)&pQp,   g_q_p);
    cudaGetSymbolAddress((void**)&pcp,   g_ctx_p);
    cudaGetSymbolAddress((void**)&pyp,   g_y_p);
    cudaGetSymbolAddress((void**)&pxp,   g_x_p);
    cudaGetSymbolAddress((void**)&php,   g_hf_p);
    cudaGetSymbolAddress((void**)&pzp,   g_z_p);
    cudaGetSymbolAddress((void**)&pmh,   g_mask_h);

    cudaFuncSetAttribute(gemm_mma,   cudaFuncAttributeMaxDynamicSharedMemorySize, GEMM_DSMEM);
    cudaFuncSetAttribute(flash_attn, cudaFuncAttributeMaxDynamicSharedMemorySize, FA_DSMEM);

    // 1) unified prep (one launch)
    prep2_k<<<PB_BIAS, 256>>>(Wq, Wk, Wv, bq, bk, bv, Wo, W1, W2, src, mask);

    // 2) QKV plane = src @ Wqkv + bqkv
    gemm_mma<<<dim3(N3 / 256, M / 128), 512, GEMM_DSMEM>>>(
        psp, pqw, nullptr, pQp, pbqkv, nullptr, nullptr, N3, D, 0);

    // 3) fused attention -> CTX plane
    flash_attn<<<dim3(S / 128, B * H), 128, FA_DSMEM>>>(pQp, pmh, pcp);

    // 4) Yh = src_p + CTX @ Wo + bo   (fp16 residual, fp16 out)
    gemm_mma<<<dim3(D / 256, M / 128), 512, GEMM_DSMEM>>>(
        pcp, pow_, nullptr, pyp, bo, nullptr, psp, D, D, 0);

    // 5) Xp = LN1(Yh)  (fp16 only)
    layernorm_k<<<M, 256>>>(pyp, ln1w, ln1b, nullptr, pxp);

    // 6) Hf plane = relu(X @ W1 + b1)
    gemm_mma<<<dim3(F / 256, M / 128), 512, GEMM_DSMEM>>>(
        pxp, p1w, nullptr, php, b1, nullptr, nullptr, F, D, 1);

    // 7) Zh = X + Hf @ W2 + b2   (fp16 residual, fp16 out)
    gemm_mma<<<dim3(D / 256, M / 128), 512, GEMM_DSMEM>>>(
        php, p2w, nullptr, pzp, b2, nullptr, pxp, D, F, 0);

    // 8) out = LN2(Zh)
    layernorm_k<<<M, 256>>>(pzp, ln2w, ln2b, out, nullptr);
}